// round 14
// baseline (speedup 1.0000x reference)
#include <cuda_runtime.h>
#include <math.h>
#include <cstdint>

#define Bb 4
#define Tt 2048
#define Ee 1024
#define Hh 64
#define ROWS (Bb*Tt)

__device__ float g_q [ROWS*Hh];
__device__ float g_kh[ROWS*Hh];
__device__ float g_kl[ROWS*Hh];
__device__ float g_vh[ROWS*Hh];
__device__ float g_vl[ROWS*Hh];
__device__ float g_wh[Ee*192];
__device__ float g_wl[Ee*192];

// ---------------------------------------------------------------------------
// Helpers
// ---------------------------------------------------------------------------
__device__ __forceinline__ uint32_t smem_u32(const void* p) {
    uint32_t a;
    asm("{ .reg .u64 t; cvta.to.shared.u64 t, %1; cvt.u32.u64 %0, t; }" : "=r"(a) : "l"(p));
    return a;
}
#define CP_ASYNC16(dst_u32, src_ptr) \
    asm volatile("cp.async.cg.shared.global [%0], [%1], 16;" :: "r"(dst_u32), "l"(src_ptr))
#define CP_COMMIT() asm volatile("cp.async.commit_group;" ::: "memory")
#define CP_WAIT0()  asm volatile("cp.async.wait_group 0;" ::: "memory")
#define CP_WAIT1()  asm volatile("cp.async.wait_group 1;" ::: "memory")

__device__ __forceinline__ uint32_t tf32_of(float x) {
    uint32_t u;
    asm("cvt.rna.tf32.f32 %0, %1;" : "=r"(u) : "f"(x));
    return u;
}
__device__ __forceinline__ void mma_tf32(float* d, const uint32_t* a, uint32_t b0, uint32_t b1) {
    asm volatile(
        "mma.sync.aligned.m16n8k8.row.col.f32.tf32.tf32.f32 "
        "{%0,%1,%2,%3}, {%4,%5,%6,%7}, {%8,%9}, {%0,%1,%2,%3};"
        : "+f"(d[0]), "+f"(d[1]), "+f"(d[2]), "+f"(d[3])
        : "r"(a[0]), "r"(a[1]), "r"(a[2]), "r"(a[3]), "r"(b0), "r"(b1));
}

// ---------------------------------------------------------------------------
// Kernel 0: split W = [Wq|Wk|Wv] into tf32 high/low parts.
// ---------------------------------------------------------------------------
__global__ __launch_bounds__(512) void wsplit(
    const float* __restrict__ Wq, const float* __restrict__ Wk,
    const float* __restrict__ Wv)
{
    int idx = blockIdx.x * 512 + threadIdx.x;       // 0 .. 196607
    int k = idx / 192, n = idx % 192;
    const float* Ws = (n < 64) ? Wq : (n < 128) ? Wk : Wv;
    float v = Ws[k * 64 + (n & 63)];
    float h = __uint_as_float(tf32_of(v));
    g_wh[idx] = h;
    g_wl[idx] = __uint_as_float(tf32_of(v - h));
}

// ---------------------------------------------------------------------------
// Kernel 1: fused QKV projection, mma.sync tf32x2. NOW 512 threads = 16
// warps (4m x 4n), warp tile 16x48 -> 4 warps/SMSP for latency hiding.
// ---------------------------------------------------------------------------
#define KCH 32
#define NCH (Ee / KCH)            // 32
#define PA 68
#define PB 200
#define STG_FLOATS (64 * PA + 2 * KCH * PB)    // 17152
#define QKV_SMEM_BYTES (2 * STG_FLOATS * 4)    // 137216

extern __shared__ float dyn_sm[];

__global__ __launch_bounds__(512, 1) void qkv_mma(
    const float* __restrict__ x,
    const float* __restrict__ bq, const float* __restrict__ bk,
    const float* __restrict__ bv)
{
    const int tid  = threadIdx.x;
    const int wid  = tid >> 5;
    const int lane = tid & 31;
    const int grp  = lane >> 2;
    const int t4   = lane & 3;
    const int wm   = wid >> 2;        // 0..3 : 16-row slice
    const int wn   = wid & 3;         // 0..3 : 48-col slice
    const int row0 = blockIdx.x * 64;

    const uint32_t sbase = smem_u32(dyn_sm);

    float d[6][4];
    #pragma unroll
    for (int t = 0; t < 6; ++t)
        { d[t][0] = 0.f; d[t][1] = 0.f; d[t][2] = 0.f; d[t][3] = 0.f; }

    auto issue = [&](int c, int s) {
        const int k0 = c * KCH;
        const uint32_t st = sbase + (uint32_t)(s * STG_FLOATS) * 4u;
        // A: 64 rows x 8 float4 = 512 float4 (one per thread)
        {
            int r = tid >> 3, c4 = tid & 7;
            CP_ASYNC16(st + (uint32_t)(r * PA + c4 * 4) * 4u,
                       x + (size_t)(row0 + r) * Ee + k0 + c4 * 4);
        }
        // Bh/Bl: 32 k-rows x 48 float4 each = 1536 -> 3 iters of 512
        #pragma unroll
        for (int it = 0; it < 3; ++it) {
            int i = tid + it * 512;
            int k = i / 48, c4 = i % 48;
            const size_t so = (size_t)(k0 + k) * 192 + c4 * 4;
            CP_ASYNC16(st + (uint32_t)(64 * PA + k * PB + c4 * 4) * 4u, g_wh + so);
            CP_ASYNC16(st + (uint32_t)(64 * PA + KCH * PB + k * PB + c4 * 4) * 4u, g_wl + so);
        }
        CP_COMMIT();
    };

    issue(0, 0);

    #pragma unroll 1
    for (int c = 0; c < NCH; ++c) {
        const int s = c & 1;
        if (c + 1 < NCH) { issue(c + 1, s ^ 1); CP_WAIT1(); }
        else             { CP_WAIT0(); }
        __syncthreads();

        const float* A  = dyn_sm + s * STG_FLOATS;
        const float* Bh = A + 64 * PA;
        const float* Bl = Bh + KCH * PB;
        const float* ar = A + (wm * 16 + grp) * PA;

        #pragma unroll
        for (int kk = 0; kk < 4; ++kk) {
            const int kb = kk * 8;
            float av0 = ar[kb + t4];
            float av1 = ar[8 * PA + kb + t4];
            float av2 = ar[kb + t4 + 4];
            float av3 = ar[8 * PA + kb + t4 + 4];
            uint32_t ah[4], al[4];
            ah[0] = tf32_of(av0); al[0] = tf32_of(av0 - __uint_as_float(ah[0]));
            ah[1] = tf32_of(av1); al[1] = tf32_of(av1 - __uint_as_float(ah[1]));
            ah[2] = tf32_of(av2); al[2] = tf32_of(av2 - __uint_as_float(ah[2]));
            ah[3] = tf32_of(av3); al[3] = tf32_of(av3 - __uint_as_float(ah[3]));

            const float* bh0p = Bh + (kb + t4) * PB + wn * 48 + grp;
            const float* bh1p = bh0p + 4 * PB;
            const float* bl0p = Bl + (kb + t4) * PB + wn * 48 + grp;
            const float* bl1p = bl0p + 4 * PB;
            #pragma unroll
            for (int tn = 0; tn < 6; ++tn) {
                uint32_t bh0 = __float_as_uint(bh0p[tn * 8]);
                uint32_t bh1 = __float_as_uint(bh1p[tn * 8]);
                uint32_t bl0 = __float_as_uint(bl0p[tn * 8]);
                uint32_t bl1 = __float_as_uint(bl1p[tn * 8]);
                mma_tf32(d[tn], ah, bh0, bh1);
                mma_tf32(d[tn], ah, bl0, bl1);
                mma_tf32(d[tn], al, bh0, bh1);
            }
        }
        __syncthreads();
    }

    const float* biases[3] = { bq, bk, bv };
    const int r_hi = row0 + wm * 16 + grp;
    #pragma unroll
    for (int tn = 0; tn < 6; ++tn) {
        int ng  = wn * 48 + tn * 8 + 2 * t4;
        int mat = ng >> 6, nc = ng & 63;
        float b0 = biases[mat][nc], b1 = biases[mat][nc + 1];
        float v00 = d[tn][0] + b0, v01 = d[tn][1] + b1;
        float v10 = d[tn][2] + b0, v11 = d[tn][3] + b1;
        size_t o0 = (size_t)r_hi * Hh + nc, o1 = (size_t)(r_hi + 8) * Hh + nc;
        if (mat == 0) {
            *(float2*)(g_q + o0) = make_float2(v00, v01);
            *(float2*)(g_q + o1) = make_float2(v10, v11);
        } else {
            float* oh = (mat == 1) ? g_kh : g_vh;
            float* ol = (mat == 1) ? g_kl : g_vl;
            float h00 = __uint_as_float(tf32_of(v00)), h01 = __uint_as_float(tf32_of(v01));
            float h10 = __uint_as_float(tf32_of(v10)), h11 = __uint_as_float(tf32_of(v11));
            *(float2*)(oh + o0) = make_float2(h00, h01);
            *(float2*)(oh + o1) = make_float2(h10, h11);
            *(float2*)(ol + o0) = make_float2(__uint_as_float(tf32_of(v00 - h00)),
                                              __uint_as_float(tf32_of(v01 - h01)));
            *(float2*)(ol + o1) = make_float2(__uint_as_float(tf32_of(v10 - h10)),
                                              __uint_as_float(tf32_of(v11 - h11)));
        }
    }
}

// ---------------------------------------------------------------------------
// Kernel 2: causal flash attention. NOW 512 threads = 16 warps: wm4=wid>>2
// (A-half0, A-half1, B-half0, B-half1) x wn=wid&3 -> each SMSP hosts 2 A- and
// 2 B-warps. Sets A and B computed in PARALLEL across warps (was sequential
// in-warp). Merged pair streaming + 2-term PV kept from R13.
// ---------------------------------------------------------------------------
#define PQ 68
#define PKk 68
#define PV 72
#define PP 20
#define PO 67
#define KVSTG (64 * (2 * PKk + 2 * PV))        // 17920 floats per stage
#define S_KH 0
#define S_KL (64 * PKk)
#define S_VH (2 * 64 * PKk)
#define S_VL (S_VH + 64 * PV)
#define OFF_Q   (2 * KVSTG)                    // 35840 : Qh 64 rows (A:0-31, B:32-63)
#define OFF_QL  (OFF_Q + 64 * PQ)              // 40192
#define OFF_P   (OFF_QL + 64 * PQ)             // 44544 : 16 warps x 16 x PP
#define OFF_MS  (OFF_P + 16 * 16 * PP)         // 49664 : 2 sets x 128
#define OFF_LS  (OFF_MS + 256)                 // 49920
#define OFF_LG  (OFF_LS + 256)                 // 50176 : 2 sets x 32
#define ATTN_SMEM_BYTES ((OFF_LG + 64) * 4)    // 200960

__global__ __launch_bounds__(512, 1) void attn_mma(float* __restrict__ out)
{
    float* sm = dyn_sm;
    const uint32_t sbase = smem_u32(sm);
    const int tid  = threadIdx.x;
    const int wid  = tid >> 5;
    const int lane = tid & 31;
    const int grp  = lane >> 2;
    const int t4   = lane & 3;
    const int wm4  = wid >> 2;          // 0..3
    const int isB  = wm4 >> 1;          // 0 = set A, 1 = set B
    const int wm   = wm4 & 1;           // 16-row half within set
    const int wn   = wid & 3;           // key slice
    const int pair = blockIdx.x;
    const int b    = blockIdx.y;

    const size_t boff = (size_t)(b * Tt) * Hh;
    const int r0 = wm * 16 + grp;       // set-local row

    const int qtA = pair, qtB = 63 - pair;
    const int qbaseA = qtA * 32, qbaseB = qtB * 32;
    const int nktA = qtA / 2 + 1, nktB = qtB / 2 + 1;   // nktA <= nktB

    const int myqbase = isB ? qbaseB : qbaseA;
    const int mynkt   = isB ? nktB : nktA;
    const int qoff    = isB ? 32 : 0;

    auto issue_kv = [&](int t0, int s) {
        const uint32_t st = sbase + (uint32_t)(s * KVSTG) * 4u;
        const size_t g0 = boff + (size_t)t0 * 64 * Hh;
        #pragma unroll
        for (int it = 0; it < 2; ++it) {
            int i = tid + it * 512;          // 0..1023
            int r = i >> 4, c4 = i & 15;
            const size_t so = g0 + r * 64 + c4 * 4;
            CP_ASYNC16(st + (uint32_t)(S_KH + r * PKk + c4 * 4) * 4u, g_kh + so);
            CP_ASYNC16(st + (uint32_t)(S_KL + r * PKk + c4 * 4) * 4u, g_kl + so);
            CP_ASYNC16(st + (uint32_t)(S_VH + r * PV + c4 * 4) * 4u, g_vh + so);
            CP_ASYNC16(st + (uint32_t)(S_VL + r * PV + c4 * 4) * 4u, g_vl + so);
        }
        CP_COMMIT();
    };

    // stage Q for BOTH tiles: rows 0..31 = A, 32..63 = B (x8 scale folded in)
    #pragma unroll
    for (int it = 0; it < 2; ++it) {
        int i = tid + it * 512;              // 0..1023
        int r = i >> 4, c4 = i & 15;
        int gq = (r < 32) ? (qbaseA + r) : (qbaseB + (r - 32));
        float4 v = *(const float4*)(g_q + boff + (size_t)gq * Hh + c4 * 4);
        float4 h, l;
        h.x = __uint_as_float(tf32_of(v.x)); l.x = 8.f * __uint_as_float(tf32_of(v.x - h.x));
        h.y = __uint_as_float(tf32_of(v.y)); l.y = 8.f * __uint_as_float(tf32_of(v.y - h.y));
        h.z = __uint_as_float(tf32_of(v.z)); l.z = 8.f * __uint_as_float(tf32_of(v.z - h.z));
        h.w = __uint_as_float(tf32_of(v.w)); l.w = 8.f * __uint_as_float(tf32_of(v.w - h.w));
        h.x *= 8.f; h.y *= 8.f; h.z *= 8.f; h.w *= 8.f;
        *(float4*)(sm + OFF_Q  + r * PQ + c4 * 4) = h;
        *(float4*)(sm + OFF_QL + r * PQ + c4 * 4) = l;
    }

    issue_kv(0, 0);

    float Of[8][4];
    #pragma unroll
    for (int nt = 0; nt < 8; ++nt)
        { Of[nt][0] = 0.f; Of[nt][1] = 0.f; Of[nt][2] = 0.f; Of[nt][3] = 0.f; }
    float m0 = -INFINITY, m1 = -INFINITY, l0 = 0.f, l1 = 0.f;

    // ---- single merged K/V stream; each warp handles its own query set ----
    #pragma unroll 1
    for (int t0 = 0; t0 < nktB; ++t0) {
        const int s = t0 & 1;
        __syncthreads();
        if (t0 + 1 < nktB) { issue_kv(t0 + 1, s ^ 1); CP_WAIT1(); }
        else               { CP_WAIT0(); }
        __syncthreads();

        if (t0 >= mynkt) continue;        // A-warps idle in the tail

        const float* Kh = sm + s * KVSTG + S_KH;
        const float* Kl = sm + s * KVSTG + S_KL;
        const float* Vh = sm + s * KVSTG + S_VH;
        const float* Vl = sm + s * KVSTG + S_VL;

        // ---- S = Qs . K^T : 3 independent accumulator sets ----
        float shh[8], shl[8], slh[8];
        #pragma unroll
        for (int i = 0; i < 8; ++i) { shh[i] = 0.f; shl[i] = 0.f; slh[i] = 0.f; }

        const float* qh = sm + OFF_Q  + (qoff + r0) * PQ;
        const float* ql = sm + OFF_QL + (qoff + r0) * PQ;
        #pragma unroll
        for (int kk = 0; kk < 8; ++kk) {
            const int kbm = kk * 8;
            uint32_t ah[4], al[4];
            ah[0] = __float_as_uint(qh[kbm + t4]);
            ah[1] = __float_as_uint(qh[8 * PQ + kbm + t4]);
            ah[2] = __float_as_uint(qh[kbm + t4 + 4]);
            ah[3] = __float_as_uint(qh[8 * PQ + kbm + t4 + 4]);
            al[0] = __float_as_uint(ql[kbm + t4]);
            al[1] = __float_as_uint(ql[8 * PQ + kbm + t4]);
            al[2] = __float_as_uint(ql[kbm + t4 + 4]);
            al[3] = __float_as_uint(ql[8 * PQ + kbm + t4 + 4]);
            #pragma unroll
            for (int nt = 0; nt < 2; ++nt) {
                const int ro = (wn * 16 + nt * 8 + grp) * PKk + kbm;
                uint32_t bh0 = __float_as_uint(Kh[ro + t4]);
                uint32_t bh1 = __float_as_uint(Kh[ro + t4 + 4]);
                uint32_t bl0 = __float_as_uint(Kl[ro + t4]);
                uint32_t bl1 = __float_as_uint(Kl[ro + t4 + 4]);
                mma_tf32(shh + 4 * nt, ah, bh0, bh1);
                mma_tf32(shl + 4 * nt, ah, bl0, bl1);
                mma_tf32(slh + 4 * nt, al, bh0, bh1);
            }
        }
        float sf[8];
        #pragma unroll
        for (int i = 0; i < 8; ++i) sf[i] = (shh[i] + shl[i]) + slh[i];

        // ---- causal mask (last tile of this set only) ----
        if (t0 == mynkt - 1) {
            const int kc = t0 * 64 + wn * 16 + 2 * t4;
            const int q0 = myqbase + r0, q1 = q0 + 8;
            #pragma unroll
            for (int nt = 0; nt < 2; ++nt) {
                int k0c = kc + nt * 8;
                if (k0c     > q0) sf[4*nt+0] = -INFINITY;
                if (k0c + 1 > q0) sf[4*nt+1] = -INFINITY;
                if (k0c     > q1) sf[4*nt+2] = -INFINITY;
                if (k0c + 1 > q1) sf[4*nt+3] = -INFINITY;
            }
        }

        // ---- online softmax (per warp-slice) ----
        float rmax0 = fmaxf(fmaxf(sf[0], sf[1]), fmaxf(sf[4], sf[5]));
        float rmax1 = fmaxf(fmaxf(sf[2], sf[3]), fmaxf(sf[6], sf[7]));
        rmax0 = fmaxf(rmax0, __shfl_xor_sync(0xffffffffu, rmax0, 1));
        rmax0 = fmaxf(rmax0, __shfl_xor_sync(0xffffffffu, rmax0, 2));
        rmax1 = fmaxf(rmax1, __shfl_xor_sync(0xffffffffu, rmax1, 1));
        rmax1 = fmaxf(rmax1, __shfl_xor_sync(0xffffffffu, rmax1, 2));

        float mn0 = fmaxf(m0, rmax0), mn1 = fmaxf(m1, rmax1);
        float sm0 = (mn0 == -INFINITY) ? 0.f : mn0;
        float sm1 = (mn1 == -INFINITY) ? 0.f : mn1;
        float corr0 = __expf(m0 - sm0);
        float corr1 = __expf(m1 - sm1);
        m0 = mn0; m1 = mn1;

        float p[8];
        p[0] = __expf(sf[0] - sm0); p[1] = __expf(sf[1] - sm0);
        p[4] = __expf(sf[4] - sm0); p[5] = __expf(sf[5] - sm0);
        p[2] = __expf(sf[2] - sm1); p[3] = __expf(sf[3] - sm1);
        p[6] = __expf(sf[6] - sm1); p[7] = __expf(sf[7] - sm1);

        float rs0 = (p[0] + p[1]) + (p[4] + p[5]);
        float rs1 = (p[2] + p[3]) + (p[6] + p[7]);
        rs0 += __shfl_xor_sync(0xffffffffu, rs0, 1);
        rs0 += __shfl_xor_sync(0xffffffffu, rs0, 2);
        rs1 += __shfl_xor_sync(0xffffffffu, rs1, 1);
        rs1 += __shfl_xor_sync(0xffffffffu, rs1, 2);
        l0 = l0 * corr0 + rs0;
        l1 = l1 * corr1 + rs1;

        #pragma unroll
        for (int nt = 0; nt < 8; ++nt) {
            Of[nt][0] *= corr0; Of[nt][1] *= corr0;
            Of[nt][2] *= corr1; Of[nt][3] *= corr1;
        }

        // ---- stage P pre-rounded to tf32 ----
        float* Pw = sm + OFF_P + wid * (16 * PP);
        #pragma unroll
        for (int nt = 0; nt < 2; ++nt) {
            *(float2*)(Pw + grp * PP + nt * 8 + 2 * t4) =
                make_float2(__uint_as_float(tf32_of(p[4*nt+0])),
                            __uint_as_float(tf32_of(p[4*nt+1])));
            *(float2*)(Pw + (grp + 8) * PP + nt * 8 + 2 * t4) =
                make_float2(__uint_as_float(tf32_of(p[4*nt+2])),
                            __uint_as_float(tf32_of(p[4*nt+3])));
        }
        __syncwarp();

        // ---- O += ph.(Vh + Vl) : 2 MMAs per step ----
        #pragma unroll
        for (int ks = 0; ks < 2; ++ks) {
            uint32_t ph[4];
            ph[0] = __float_as_uint(Pw[grp * PP + ks * 8 + t4]);
            ph[1] = __float_as_uint(Pw[(grp + 8) * PP + ks * 8 + t4]);
            ph[2] = __float_as_uint(Pw[grp * PP + ks * 8 + t4 + 4]);
            ph[3] = __float_as_uint(Pw[(grp + 8) * PP + ks * 8 + t4 + 4]);

            const int vo = (wn * 16 + ks * 8 + t4) * PV + grp;
            #pragma unroll
            for (int nt = 0; nt < 8; ++nt) {
                uint32_t bh0 = __float_as_uint(Vh[vo + nt * 8]);
                uint32_t bh1 = __float_as_uint(Vh[vo + 4 * PV + nt * 8]);
                uint32_t bl0 = __float_as_uint(Vl[vo + nt * 8]);
                uint32_t bl1 = __float_as_uint(Vl[vo + 4 * PV + nt * 8]);
                mma_tf32(Of[nt], ph, bh0, bh1);
                mma_tf32(Of[nt], ph, bl0, bl1);
            }
        }
        __syncwarp();
    }

    // ---- merge 4 wn-slices (each warp handles its own set) ----
    __syncthreads();
    const int sb = isB ? 128 : 0;
    if (t4 == 0) {
        int si = (wm * 4 + wn) * 16 + grp;
        sm[OFF_MS + sb + si]     = m0; sm[OFF_MS + sb + si + 8] = m1;
        sm[OFF_LS + sb + si]     = l0; sm[OFF_LS + sb + si + 8] = l1;
    }
    __syncthreads();

    {
        float mg0 = -INFINITY, mg1 = -INFINITY;
        #pragma unroll
        for (int w = 0; w < 4; ++w) {
            mg0 = fmaxf(mg0, sm[OFF_MS + sb + (wm * 4 + w) * 16 + grp]);
            mg1 = fmaxf(mg1, sm[OFF_MS + sb + (wm * 4 + w) * 16 + grp + 8]);
        }
        float lg0 = 0.f, lg1 = 0.f;
        #pragma unroll
        for (int w = 0; w < 4; ++w) {
            lg0 += sm[OFF_LS + sb + (wm * 4 + w) * 16 + grp]     * __expf(sm[OFF_MS + sb + (wm * 4 + w) * 16 + grp]     - mg0);
            lg1 += sm[OFF_LS + sb + (wm * 4 + w) * 16 + grp + 8] * __expf(sm[OFF_MS + sb + (wm * 4 + w) * 16 + grp + 8] - mg1);
        }
        float w0 = __expf(m0 - mg0);
        float w1 = __expf(m1 - mg1);
        if (wn == 0 && t4 == 0) {
            sm[OFF_LG + isB * 32 + r0]     = lg0;
            sm[OFF_LG + isB * 32 + r0 + 8] = lg1;
        }
        #pragma unroll
        for (int nt = 0; nt < 8; ++nt) {
            Of[nt][0] *= w0; Of[nt][1] *= w0;
            Of[nt][2] *= w1; Of[nt][3] *= w1;
        }
    }

    float* acc = (isB ? sm + KVSTG : sm);   // A -> stage0, B -> stage1 (free)
    #pragma unroll 1
    for (int r = 0; r < 4; ++r) {
        __syncthreads();
        if (wn == r) {
            #pragma unroll
            for (int nt = 0; nt < 8; ++nt) {
                int a0 = r0 * PO + nt * 8 + 2 * t4;
                int a1 = (r0 + 8) * PO + nt * 8 + 2 * t4;
                if (r == 0) {
                    acc[a0] = Of[nt][0]; acc[a0 + 1] = Of[nt][1];
                    acc[a1] = Of[nt][2]; acc[a1 + 1] = Of[nt][3];
                } else {
                    acc[a0] += Of[nt][0]; acc[a0 + 1] += Of[nt][1];
                    acc[a1] += Of[nt][2]; acc[a1 + 1] += Of[nt][3];
                }
            }
        }
    }
    __syncthreads();

    float* accA = sm;
    float* accB = sm + KVSTG;
    float* opA = out + boff + (size_t)qbaseA * Hh;
    float* opB = out + boff + (size_t)qbaseB * Hh;
    #pragma unroll
    for (int it = 0; it < 4; ++it) {
        int i = tid + it * 512;             // 0..2047
        int r = i >> 6, dd = i & 63;
        opA[i] = accA[r * PO + dd] * __fdividef(1.0f, sm[OFF_LG + r]);
        opB[i] = accB[r * PO + dd] * __fdividef(1.0f, sm[OFF_LG + 32 + r]);
    }
}

extern "C" void kernel_launch(void* const* d_in, const int* in_sizes, int n_in,
                              void* d_out, int out_size)
{
    const float* x  = (const float*)d_in[0];
    const float* Wq = (const float*)d_in[1];
    const float* bq = (const float*)d_in[2];
    const float* Wk = (const float*)d_in[3];
    const float* bk = (const float*)d_in[4];
    const float* Wv = (const float*)d_in[5];
    const float* bv = (const float*)d_in[6];
    float* out = (float*)d_out;

    cudaFuncSetAttribute(qkv_mma, cudaFuncAttributeMaxDynamicSharedMemorySize,
                         QKV_SMEM_BYTES);
    cudaFuncSetAttribute(attn_mma, cudaFuncAttributeMaxDynamicSharedMemorySize,
                         ATTN_SMEM_BYTES);

    wsplit<<<384, 512>>>(Wq, Wk, Wv);
    qkv_mma<<<128, 512, QKV_SMEM_BYTES>>>(x, bq, bk, bv);
    attn_mma<<<dim3(32, 4), 512, ATTN_SMEM_BYTES>>>(out);
}

// round 15
// speedup vs baseline: 1.0052x; 1.0052x over previous
#include <cuda_runtime.h>
#include <math.h>
#include <cstdint>

#define Bb 4
#define Tt 2048
#define Ee 1024
#define Hh 64
#define ROWS (Bb*Tt)

__device__ float g_q [ROWS*Hh];
__device__ float g_kh[ROWS*Hh];
__device__ float g_kl[ROWS*Hh];
__device__ float g_vh[ROWS*Hh];
__device__ float g_vl[ROWS*Hh];
__device__ float g_wh[Ee*192];
__device__ float g_wl[Ee*192];

// ---------------------------------------------------------------------------
// Helpers
// ---------------------------------------------------------------------------
__device__ __forceinline__ uint32_t smem_u32(const void* p) {
    uint32_t a;
    asm("{ .reg .u64 t; cvta.to.shared.u64 t, %1; cvt.u32.u64 %0, t; }" : "=r"(a) : "l"(p));
    return a;
}
#define CP_ASYNC16(dst_u32, src_ptr) \
    asm volatile("cp.async.cg.shared.global [%0], [%1], 16;" :: "r"(dst_u32), "l"(src_ptr))
#define CP_COMMIT() asm volatile("cp.async.commit_group;" ::: "memory")
#define CP_WAIT0()  asm volatile("cp.async.wait_group 0;" ::: "memory")
#define CP_WAIT1()  asm volatile("cp.async.wait_group 1;" ::: "memory")

__device__ __forceinline__ uint32_t tf32_of(float x) {
    uint32_t u;
    asm("cvt.rna.tf32.f32 %0, %1;" : "=r"(u) : "f"(x));
    return u;
}
__device__ __forceinline__ void mma_tf32(float* d, const uint32_t* a, uint32_t b0, uint32_t b1) {
    asm volatile(
        "mma.sync.aligned.m16n8k8.row.col.f32.tf32.tf32.f32 "
        "{%0,%1,%2,%3}, {%4,%5,%6,%7}, {%8,%9}, {%0,%1,%2,%3};"
        : "+f"(d[0]), "+f"(d[1]), "+f"(d[2]), "+f"(d[3])
        : "r"(a[0]), "r"(a[1]), "r"(a[2]), "r"(a[3]), "r"(b0), "r"(b1));
}

// ---------------------------------------------------------------------------
// Kernel 0: split W = [Wq|Wk|Wv] into tf32 high/low parts.
// ---------------------------------------------------------------------------
__global__ __launch_bounds__(512) void wsplit(
    const float* __restrict__ Wq, const float* __restrict__ Wk,
    const float* __restrict__ Wv)
{
    int idx = blockIdx.x * 512 + threadIdx.x;       // 0 .. 196607
    int k = idx / 192, n = idx % 192;
    const float* Ws = (n < 64) ? Wq : (n < 128) ? Wk : Wv;
    float v = Ws[k * 64 + (n & 63)];
    float h = __uint_as_float(tf32_of(v));
    g_wh[idx] = h;
    g_wl[idx] = __uint_as_float(tf32_of(v - h));
}

// ---------------------------------------------------------------------------
// Kernel 1: fused QKV projection, mma.sync tf32x2. 256 thr = 8 warps with
// warp tile 32x48 (wm 2 x wn 4): B-fragment loads amortized over 32 rows
// -> per-kk LDS 52 -> 32 (B re-read x2 only). Same MMA count as R13.
// ---------------------------------------------------------------------------
#define KCH 32
#define NCH (Ee / KCH)            // 32
#define PA 68
#define PB 200
#define STG_FLOATS (64 * PA + 2 * KCH * PB)    // 17152
#define QKV_SMEM_BYTES (2 * STG_FLOATS * 4)    // 137216

extern __shared__ float dyn_sm[];

__global__ __launch_bounds__(256, 1) void qkv_mma(
    const float* __restrict__ x,
    const float* __restrict__ bq, const float* __restrict__ bk,
    const float* __restrict__ bv)
{
    const int tid  = threadIdx.x;
    const int wid  = tid >> 5;
    const int lane = tid & 31;
    const int grp  = lane >> 2;
    const int t4   = lane & 3;
    const int wm   = wid >> 2;        // 0..1 : 32-row slice
    const int wn   = wid & 3;         // 0..3 : 48-col slice
    const int row0 = blockIdx.x * 64;

    const uint32_t sbase = smem_u32(dyn_sm);

    float d[2][6][4];
    #pragma unroll
    for (int f = 0; f < 2; ++f)
        #pragma unroll
        for (int t = 0; t < 6; ++t)
            { d[f][t][0] = 0.f; d[f][t][1] = 0.f; d[f][t][2] = 0.f; d[f][t][3] = 0.f; }

    auto issue = [&](int c, int s) {
        const int k0 = c * KCH;
        const uint32_t st = sbase + (uint32_t)(s * STG_FLOATS) * 4u;
        // A: 64 rows x 8 float4 = 512 float4 -> 2 iters
        #pragma unroll
        for (int it = 0; it < 2; ++it) {
            int i = tid + it * 256;
            int r = i >> 3, c4 = i & 7;
            CP_ASYNC16(st + (uint32_t)(r * PA + c4 * 4) * 4u,
                       x + (size_t)(row0 + r) * Ee + k0 + c4 * 4);
        }
        // Bh/Bl: 32 k-rows x 48 float4 each -> 6 iters
        #pragma unroll
        for (int it = 0; it < 6; ++it) {
            int i = tid + it * 256;
            int k = i / 48, c4 = i % 48;
            const size_t so = (size_t)(k0 + k) * 192 + c4 * 4;
            CP_ASYNC16(st + (uint32_t)(64 * PA + k * PB + c4 * 4) * 4u, g_wh + so);
            CP_ASYNC16(st + (uint32_t)(64 * PA + KCH * PB + k * PB + c4 * 4) * 4u, g_wl + so);
        }
        CP_COMMIT();
    };

    issue(0, 0);

    #pragma unroll 1
    for (int c = 0; c < NCH; ++c) {
        const int s = c & 1;
        if (c + 1 < NCH) { issue(c + 1, s ^ 1); CP_WAIT1(); }
        else             { CP_WAIT0(); }
        __syncthreads();

        const float* A  = dyn_sm + s * STG_FLOATS;
        const float* Bh = A + 64 * PA;
        const float* Bl = Bh + KCH * PB;

        #pragma unroll
        for (int kk = 0; kk < 4; ++kk) {
            const int kb = kk * 8;
            uint32_t ah[2][4], al[2][4];
            #pragma unroll
            for (int f = 0; f < 2; ++f) {
                const float* ar = A + (wm * 32 + f * 16 + grp) * PA;
                float av0 = ar[kb + t4];
                float av1 = ar[8 * PA + kb + t4];
                float av2 = ar[kb + t4 + 4];
                float av3 = ar[8 * PA + kb + t4 + 4];
                ah[f][0] = tf32_of(av0); al[f][0] = tf32_of(av0 - __uint_as_float(ah[f][0]));
                ah[f][1] = tf32_of(av1); al[f][1] = tf32_of(av1 - __uint_as_float(ah[f][1]));
                ah[f][2] = tf32_of(av2); al[f][2] = tf32_of(av2 - __uint_as_float(ah[f][2]));
                ah[f][3] = tf32_of(av3); al[f][3] = tf32_of(av3 - __uint_as_float(ah[f][3]));
            }

            const float* bh0p = Bh + (kb + t4) * PB + wn * 48 + grp;
            const float* bh1p = bh0p + 4 * PB;
            const float* bl0p = Bl + (kb + t4) * PB + wn * 48 + grp;
            const float* bl1p = bl0p + 4 * PB;
            #pragma unroll
            for (int tn = 0; tn < 6; ++tn) {
                uint32_t bh0 = __float_as_uint(bh0p[tn * 8]);
                uint32_t bh1 = __float_as_uint(bh1p[tn * 8]);
                uint32_t bl0 = __float_as_uint(bl0p[tn * 8]);
                uint32_t bl1 = __float_as_uint(bl1p[tn * 8]);
                #pragma unroll
                for (int f = 0; f < 2; ++f) {
                    mma_tf32(d[f][tn], ah[f], bh0, bh1);
                    mma_tf32(d[f][tn], ah[f], bl0, bl1);
                    mma_tf32(d[f][tn], al[f], bh0, bh1);
                }
            }
        }
        __syncthreads();
    }

    const float* biases[3] = { bq, bk, bv };
    #pragma unroll
    for (int f = 0; f < 2; ++f) {
        const int r_hi = row0 + wm * 32 + f * 16 + grp;
        #pragma unroll
        for (int tn = 0; tn < 6; ++tn) {
            int ng  = wn * 48 + tn * 8 + 2 * t4;
            int mat = ng >> 6, nc = ng & 63;
            float b0 = biases[mat][nc], b1 = biases[mat][nc + 1];
            float v00 = d[f][tn][0] + b0, v01 = d[f][tn][1] + b1;
            float v10 = d[f][tn][2] + b0, v11 = d[f][tn][3] + b1;
            size_t o0 = (size_t)r_hi * Hh + nc, o1 = (size_t)(r_hi + 8) * Hh + nc;
            if (mat == 0) {
                *(float2*)(g_q + o0) = make_float2(v00, v01);
                *(float2*)(g_q + o1) = make_float2(v10, v11);
            } else {
                float* oh = (mat == 1) ? g_kh : g_vh;
                float* ol = (mat == 1) ? g_kl : g_vl;
                float h00 = __uint_as_float(tf32_of(v00)), h01 = __uint_as_float(tf32_of(v01));
                float h10 = __uint_as_float(tf32_of(v10)), h11 = __uint_as_float(tf32_of(v11));
                *(float2*)(oh + o0) = make_float2(h00, h01);
                *(float2*)(oh + o1) = make_float2(h10, h11);
                *(float2*)(ol + o0) = make_float2(__uint_as_float(tf32_of(v00 - h00)),
                                                  __uint_as_float(tf32_of(v01 - h01)));
                *(float2*)(ol + o1) = make_float2(__uint_as_float(tf32_of(v10 - h10)),
                                                  __uint_as_float(tf32_of(v11 - h11)));
            }
        }
    }
}

// ---------------------------------------------------------------------------
// Kernel 2: causal flash attention — EXACT R13 configuration (best measured).
// 256 thr, merged pair streaming, 3-acc S-phase, 2-term PV.
// ---------------------------------------------------------------------------
#define PQ 68
#define PKk 68
#define PV 72
#define PP 20
#define PO 67
#define KVSTG (64 * (2 * PKk + 2 * PV))        // 17920 floats per stage
#define S_KH 0
#define S_KL (64 * PKk)
#define S_VH (2 * 64 * PKk)
#define S_VL (S_VH + 64 * PV)
#define OFF_Q   (2 * KVSTG)
#define OFF_QL  (OFF_Q + 64 * PQ)
#define OFF_P   (OFF_QL + 64 * PQ)
#define OFF_MS  (OFF_P + 8 * 16 * PP)
#define OFF_LS  (OFF_MS + 256)
#define OFF_LG  (OFF_LS + 256)
#define ATTN_SMEM_BYTES ((OFF_LG + 64) * 4)    // 190720

__global__ __launch_bounds__(256, 1) void attn_mma(float* __restrict__ out)
{
    float* sm = dyn_sm;
    const uint32_t sbase = smem_u32(sm);
    const int tid  = threadIdx.x;
    const int wid  = tid >> 5;
    const int lane = tid & 31;
    const int grp  = lane >> 2;
    const int t4   = lane & 3;
    const int wm   = wid & 1;
    const int wn   = wid >> 1;
    const int pair = blockIdx.x;
    const int b    = blockIdx.y;

    const size_t boff = (size_t)(b * Tt) * Hh;
    const int r0 = wm * 16 + grp;

    const int qtA = pair, qtB = 63 - pair;
    const int qbaseA = qtA * 32, qbaseB = qtB * 32;
    const int nktA = qtA / 2 + 1, nktB = qtB / 2 + 1;

    auto issue_kv = [&](int t0, int s) {
        const uint32_t st = sbase + (uint32_t)(s * KVSTG) * 4u;
        const size_t g0 = boff + (size_t)t0 * 64 * Hh;
        #pragma unroll
        for (int it = 0; it < 4; ++it) {
            int i = tid + it * 256;
            int r = i >> 4, c4 = i & 15;
            const size_t so = g0 + r * 64 + c4 * 4;
            CP_ASYNC16(st + (uint32_t)(S_KH + r * PKk + c4 * 4) * 4u, g_kh + so);
            CP_ASYNC16(st + (uint32_t)(S_KL + r * PKk + c4 * 4) * 4u, g_kl + so);
            CP_ASYNC16(st + (uint32_t)(S_VH + r * PV + c4 * 4) * 4u, g_vh + so);
            CP_ASYNC16(st + (uint32_t)(S_VL + r * PV + c4 * 4) * 4u, g_vl + so);
        }
        CP_COMMIT();
    };

    #pragma unroll
    for (int it = 0; it < 4; ++it) {
        int i = tid + it * 256;
        int r = i >> 4, c4 = i & 15;
        int gq = (r < 32) ? (qbaseA + r) : (qbaseB + (r - 32));
        float4 v = *(const float4*)(g_q + boff + (size_t)gq * Hh + c4 * 4);
        float4 h, l;
        h.x = __uint_as_float(tf32_of(v.x)); l.x = 8.f * __uint_as_float(tf32_of(v.x - h.x));
        h.y = __uint_as_float(tf32_of(v.y)); l.y = 8.f * __uint_as_float(tf32_of(v.y - h.y));
        h.z = __uint_as_float(tf32_of(v.z)); l.z = 8.f * __uint_as_float(tf32_of(v.z - h.z));
        h.w = __uint_as_float(tf32_of(v.w)); l.w = 8.f * __uint_as_float(tf32_of(v.w - h.w));
        h.x *= 8.f; h.y *= 8.f; h.z *= 8.f; h.w *= 8.f;
        *(float4*)(sm + OFF_Q  + r * PQ + c4 * 4) = h;
        *(float4*)(sm + OFF_QL + r * PQ + c4 * 4) = l;
    }

    issue_kv(0, 0);

    float OfA[8][4], OfB[8][4];
    #pragma unroll
    for (int nt = 0; nt < 8; ++nt) {
        OfA[nt][0] = 0.f; OfA[nt][1] = 0.f; OfA[nt][2] = 0.f; OfA[nt][3] = 0.f;
        OfB[nt][0] = 0.f; OfB[nt][1] = 0.f; OfB[nt][2] = 0.f; OfB[nt][3] = 0.f;
    }
    float mA0 = -INFINITY, mA1 = -INFINITY, lA0 = 0.f, lA1 = 0.f;
    float mB0 = -INFINITY, mB1 = -INFINITY, lB0 = 0.f, lB1 = 0.f;

    auto tile_compute = [&](int t0, int qoff, int qbase, int nkt,
                            const float* Kh, const float* Kl,
                            const float* Vh, const float* Vl,
                            float (&Of)[8][4],
                            float& m0, float& m1, float& l0, float& l1) {
        float shh[8], shl[8], slh[8];
        #pragma unroll
        for (int i = 0; i < 8; ++i) { shh[i] = 0.f; shl[i] = 0.f; slh[i] = 0.f; }

        const float* qh = sm + OFF_Q  + (qoff + r0) * PQ;
        const float* ql = sm + OFF_QL + (qoff + r0) * PQ;
        #pragma unroll
        for (int kk = 0; kk < 8; ++kk) {
            const int kbm = kk * 8;
            uint32_t ah[4], al[4];
            ah[0] = __float_as_uint(qh[kbm + t4]);
            ah[1] = __float_as_uint(qh[8 * PQ + kbm + t4]);
            ah[2] = __float_as_uint(qh[kbm + t4 + 4]);
            ah[3] = __float_as_uint(qh[8 * PQ + kbm + t4 + 4]);
            al[0] = __float_as_uint(ql[kbm + t4]);
            al[1] = __float_as_uint(ql[8 * PQ + kbm + t4]);
            al[2] = __float_as_uint(ql[kbm + t4 + 4]);
            al[3] = __float_as_uint(ql[8 * PQ + kbm + t4 + 4]);
            #pragma unroll
            for (int nt = 0; nt < 2; ++nt) {
                const int ro = (wn * 16 + nt * 8 + grp) * PKk + kbm;
                uint32_t bh0 = __float_as_uint(Kh[ro + t4]);
                uint32_t bh1 = __float_as_uint(Kh[ro + t4 + 4]);
                uint32_t bl0 = __float_as_uint(Kl[ro + t4]);
                uint32_t bl1 = __float_as_uint(Kl[ro + t4 + 4]);
                mma_tf32(shh + 4 * nt, ah, bh0, bh1);
                mma_tf32(shl + 4 * nt, ah, bl0, bl1);
                mma_tf32(slh + 4 * nt, al, bh0, bh1);
            }
        }
        float sf[8];
        #pragma unroll
        for (int i = 0; i < 8; ++i) sf[i] = (shh[i] + shl[i]) + slh[i];

        if (t0 == nkt - 1) {
            const int kc = t0 * 64 + wn * 16 + 2 * t4;
            const int q0 = qbase + r0, q1 = q0 + 8;
            #pragma unroll
            for (int nt = 0; nt < 2; ++nt) {
                int k0c = kc + nt * 8;
                if (k0c     > q0) sf[4*nt+0] = -INFINITY;
                if (k0c + 1 > q0) sf[4*nt+1] = -INFINITY;
                if (k0c     > q1) sf[4*nt+2] = -INFINITY;
                if (k0c + 1 > q1) sf[4*nt+3] = -INFINITY;
            }
        }

        float rmax0 = fmaxf(fmaxf(sf[0], sf[1]), fmaxf(sf[4], sf[5]));
        float rmax1 = fmaxf(fmaxf(sf[2], sf[3]), fmaxf(sf[6], sf[7]));
        rmax0 = fmaxf(rmax0, __shfl_xor_sync(0xffffffffu, rmax0, 1));
        rmax0 = fmaxf(rmax0, __shfl_xor_sync(0xffffffffu, rmax0, 2));
        rmax1 = fmaxf(rmax1, __shfl_xor_sync(0xffffffffu, rmax1, 1));
        rmax1 = fmaxf(rmax1, __shfl_xor_sync(0xffffffffu, rmax1, 2));

        float mn0 = fmaxf(m0, rmax0), mn1 = fmaxf(m1, rmax1);
        float sm0 = (mn0 == -INFINITY) ? 0.f : mn0;
        float sm1 = (mn1 == -INFINITY) ? 0.f : mn1;
        float corr0 = __expf(m0 - sm0);
        float corr1 = __expf(m1 - sm1);
        m0 = mn0; m1 = mn1;

        float p[8];
        p[0] = __expf(sf[0] - sm0); p[1] = __expf(sf[1] - sm0);
        p[4] = __expf(sf[4] - sm0); p[5] = __expf(sf[5] - sm0);
        p[2] = __expf(sf[2] - sm1); p[3] = __expf(sf[3] - sm1);
        p[6] = __expf(sf[6] - sm1); p[7] = __expf(sf[7] - sm1);

        float rs0 = (p[0] + p[1]) + (p[4] + p[5]);
        float rs1 = (p[2] + p[3]) + (p[6] + p[7]);
        rs0 += __shfl_xor_sync(0xffffffffu, rs0, 1);
        rs0 += __shfl_xor_sync(0xffffffffu, rs0, 2);
        rs1 += __shfl_xor_sync(0xffffffffu, rs1, 1);
        rs1 += __shfl_xor_sync(0xffffffffu, rs1, 2);
        l0 = l0 * corr0 + rs0;
        l1 = l1 * corr1 + rs1;

        #pragma unroll
        for (int nt = 0; nt < 8; ++nt) {
            Of[nt][0] *= corr0; Of[nt][1] *= corr0;
            Of[nt][2] *= corr1; Of[nt][3] *= corr1;
        }

        float* Pw = sm + OFF_P + wid * (16 * PP);
        #pragma unroll
        for (int nt = 0; nt < 2; ++nt) {
            *(float2*)(Pw + grp * PP + nt * 8 + 2 * t4) =
                make_float2(__uint_as_float(tf32_of(p[4*nt+0])),
                            __uint_as_float(tf32_of(p[4*nt+1])));
            *(float2*)(Pw + (grp + 8) * PP + nt * 8 + 2 * t4) =
                make_float2(__uint_as_float(tf32_of(p[4*nt+2])),
                            __uint_as_float(tf32_of(p[4*nt+3])));
        }
        __syncwarp();

        #pragma unroll
        for (int ks = 0; ks < 2; ++ks) {
            uint32_t ph[4];
            ph[0] = __float_as_uint(Pw[grp * PP + ks * 8 + t4]);
            ph[1] = __float_as_uint(Pw[(grp + 8) * PP + ks * 8 + t4]);
            ph[2] = __float_as_uint(Pw[grp * PP + ks * 8 + t4 + 4]);
            ph[3] = __float_as_uint(Pw[(grp + 8) * PP + ks * 8 + t4 + 4]);

            const int vo = (wn * 16 + ks * 8 + t4) * PV + grp;
            #pragma unroll
            for (int nt = 0; nt < 8; ++nt) {
                uint32_t bh0 = __float_as_uint(Vh[vo + nt * 8]);
                uint32_t bh1 = __float_as_uint(Vh[vo + 4 * PV + nt * 8]);
                uint32_t bl0 = __float_as_uint(Vl[vo + nt * 8]);
                uint32_t bl1 = __float_as_uint(Vl[vo + 4 * PV + nt * 8]);
                mma_tf32(Of[nt], ph, bh0, bh1);
                mma_tf32(Of[nt], ph, bl0, bl1);
            }
        }
        __syncwarp();
    };

    #pragma unroll 1
    for (int t0 = 0; t0 < nktB; ++t0) {
        const int s = t0 & 1;
        __syncthreads();
        if (t0 + 1 < nktB) { issue_kv(t0 + 1, s ^ 1); CP_WAIT1(); }
        else               { CP_WAIT0(); }
        __syncthreads();

        const float* Kh = sm + s * KVSTG + S_KH;
        const float* Kl = sm + s * KVSTG + S_KL;
        const float* Vh = sm + s * KVSTG + S_VH;
        const float* Vl = sm + s * KVSTG + S_VL;

        tile_compute(t0, 32, qbaseB, nktB, Kh, Kl, Vh, Vl, OfB, mB0, mB1, lB0, lB1);
        if (t0 < nktA)
            tile_compute(t0, 0, qbaseA, nktA, Kh, Kl, Vh, Vl, OfA, mA0, mA1, lA0, lA1);
    }

    __syncthreads();
    if (t4 == 0) {
        int si = (wm * 4 + wn) * 16 + grp;
        sm[OFF_MS + si]           = mA0; sm[OFF_MS + si + 8]       = mA1;
        sm[OFF_LS + si]           = lA0; sm[OFF_LS + si + 8]       = lA1;
        sm[OFF_MS + 128 + si]     = mB0; sm[OFF_MS + 128 + si + 8] = mB1;
        sm[OFF_LS + 128 + si]     = lB0; sm[OFF_LS + 128 + si + 8] = lB1;
    }
    __syncthreads();

    float wA0, wA1, wB0, wB1;
    {
        float mg0 = -INFINITY, mg1 = -INFINITY;
        #pragma unroll
        for (int w = 0; w < 4; ++w) {
            mg0 = fmaxf(mg0, sm[OFF_MS + (wm * 4 + w) * 16 + grp]);
            mg1 = fmaxf(mg1, sm[OFF_MS + (wm * 4 + w) * 16 + grp + 8]);
        }
        float lg0 = 0.f, lg1 = 0.f;
        #pragma unroll
        for (int w = 0; w < 4; ++w) {
            lg0 += sm[OFF_LS + (wm * 4 + w) * 16 + grp]     * __expf(sm[OFF_MS + (wm * 4 + w) * 16 + grp]     - mg0);
            lg1 += sm[OFF_LS + (wm * 4 + w) * 16 + grp + 8] * __expf(sm[OFF_MS + (wm * 4 + w) * 16 + grp + 8] - mg1);
        }
        wA0 = __expf(mA0 - mg0);
        wA1 = __expf(mA1 - mg1);
        if (wn == 0 && t4 == 0) { sm[OFF_LG + r0] = lg0; sm[OFF_LG + r0 + 8] = lg1; }
    }
    {
        float mg0 = -INFINITY, mg1 = -INFINITY;
        #pragma unroll
        for (int w = 0; w < 4; ++w) {
            mg0 = fmaxf(mg0, sm[OFF_MS + 128 + (wm * 4 + w) * 16 + grp]);
            mg1 = fmaxf(mg1, sm[OFF_MS + 128 + (wm * 4 + w) * 16 + grp + 8]);
        }
        float lg0 = 0.f, lg1 = 0.f;
        #pragma unroll
        for (int w = 0; w < 4; ++w) {
            lg0 += sm[OFF_LS + 128 + (wm * 4 + w) * 16 + grp]     * __expf(sm[OFF_MS + 128 + (wm * 4 + w) * 16 + grp]     - mg0);
            lg1 += sm[OFF_LS + 128 + (wm * 4 + w) * 16 + grp + 8] * __expf(sm[OFF_MS + 128 + (wm * 4 + w) * 16 + grp + 8] - mg1);
        }
        wB0 = __expf(mB0 - mg0);
        wB1 = __expf(mB1 - mg1);
        if (wn == 0 && t4 == 0) { sm[OFF_LG + 32 + r0] = lg0; sm[OFF_LG + 32 + r0 + 8] = lg1; }
    }
    #pragma unroll
    for (int nt = 0; nt < 8; ++nt) {
        OfA[nt][0] *= wA0; OfA[nt][1] *= wA0;
        OfA[nt][2] *= wA1; OfA[nt][3] *= wA1;
        OfB[nt][0] *= wB0; OfB[nt][1] *= wB0;
        OfB[nt][2] *= wB1; OfB[nt][3] *= wB1;
    }

    float* accA = sm;
    float* accB = sm + KVSTG;
    #pragma unroll 1
    for (int r = 0; r < 4; ++r) {
        __syncthreads();
        if (wn == r) {
            #pragma unroll
            for (int nt = 0; nt < 8; ++nt) {
                int a0 = r0 * PO + nt * 8 + 2 * t4;
                int a1 = (r0 + 8) * PO + nt * 8 + 2 * t4;
                if (r == 0) {
                    accA[a0] = OfA[nt][0]; accA[a0 + 1] = OfA[nt][1];
                    accA[a1] = OfA[nt][2]; accA[a1 + 1] = OfA[nt][3];
                    accB[a0] = OfB[nt][0]; accB[a0 + 1] = OfB[nt][1];
                    accB[a1] = OfB[nt][2]; accB[a1 + 1] = OfB[nt][3];
                } else {
                    accA[a0] += OfA[nt][0]; accA[a0 + 1] += OfA[nt][1];
                    accA[a1] += OfA[nt][2]; accA[a1 + 1] += OfA[nt][3];
                    accB[a0] += OfB[nt][0]; accB[a0 + 1] += OfB[nt][1];
                    accB[a1] += OfB[nt][2]; accB[a1 + 1] += OfB[nt][3];
                }
            }
        }
    }
    __syncthreads();

    float* opA = out + boff + (size_t)qbaseA * Hh;
    float* opB = out + boff + (size_t)qbaseB * Hh;
    #pragma unroll
    for (int it = 0; it < 8; ++it) {
        int i = tid + it * 256;
        int r = i >> 6, dd = i & 63;
        opA[i] = accA[r * PO + dd] * __fdividef(1.0f, sm[OFF_LG + r]);
        opB[i] = accB[r * PO + dd] * __fdividef(1.0f, sm[OFF_LG + 32 + r]);
    }
}

extern "C" void kernel_launch(void* const* d_in, const int* in_sizes, int n_in,
                              void* d_out, int out_size)
{
    const float* x  = (const float*)d_in[0];
    const float* Wq = (const float*)d_in[1];
    const float* bq = (const float*)d_in[2];
    const float* Wk = (const float*)d_in[3];
    const float* bk = (const float*)d_in[4];
    const float* Wv = (const float*)d_in[5];
    const float* bv = (const float*)d_in[6];
    float* out = (float*)d_out;

    cudaFuncSetAttribute(qkv_mma, cudaFuncAttributeMaxDynamicSharedMemorySize,
                         QKV_SMEM_BYTES);
    cudaFuncSetAttribute(attn_mma, cudaFuncAttributeMaxDynamicSharedMemorySize,
                         ATTN_SMEM_BYTES);

    wsplit<<<384, 512>>>(Wq, Wk, Wv);
    qkv_mma<<<128, 256, QKV_SMEM_BYTES>>>(x, bq, bk, bv);
    attn_mma<<<dim3(32, 4), 256, ATTN_SMEM_BYTES>>>(out);
}

// round 16
// speedup vs baseline: 1.2999x; 1.2931x over previous
#include <cuda_runtime.h>
#include <cuda_bf16.h>
#include <math.h>
#include <cstdint>

#define Bb 4
#define Tt 2048
#define Ee 1024
#define Hh 64
#define ROWS (Bb*Tt)

// packed bf16-pair operands (u32 = 2 bf16)
__device__ uint32_t       g_qph[ROWS*32], g_qpl[ROWS*32];   // Q (x8 folded), packed along dim
__device__ uint32_t       g_kph[ROWS*32], g_kpl[ROWS*32];   // K packed along dim
__device__ unsigned short g_vth[ROWS*Hh], g_vtl[ROWS*Hh];   // V^T  [b][dim][key]
__device__ uint32_t       g_wph[192*512], g_wpl[192*512];   // W^T packed along k: [n][kpair]

// ---------------------------------------------------------------------------
// Helpers
// ---------------------------------------------------------------------------
__device__ __forceinline__ uint32_t smem_u32(const void* p) {
    uint32_t a;
    asm("{ .reg .u64 t; cvta.to.shared.u64 t, %1; cvt.u32.u64 %0, t; }" : "=r"(a) : "l"(p));
    return a;
}
#define CP_ASYNC16(dst_u32, src_ptr) \
    asm volatile("cp.async.cg.shared.global [%0], [%1], 16;" :: "r"(dst_u32), "l"(src_ptr))
#define CP_COMMIT() asm volatile("cp.async.commit_group;" ::: "memory")
#define CP_WAIT0()  asm volatile("cp.async.wait_group 0;" ::: "memory")
#define CP_WAIT1()  asm volatile("cp.async.wait_group 1;" ::: "memory")

__device__ __forceinline__ uint32_t pk_bf16(float lo, float hi) {
    uint32_t r;
    asm("cvt.rn.bf16x2.f32 %0, %1, %2;" : "=r"(r) : "f"(hi), "f"(lo));
    return r;
}
__device__ __forceinline__ float lo_f(uint32_t p) { return __uint_as_float(p << 16); }
__device__ __forceinline__ float hi_f(uint32_t p) { return __uint_as_float(p & 0xFFFF0000u); }
// split (v0,v1) into high-pack (returned) and low-pack (residuals)
__device__ __forceinline__ uint32_t split_pk(float v0, float v1, uint32_t& lpk) {
    uint32_t h = pk_bf16(v0, v1);
    lpk = pk_bf16(v0 - lo_f(h), v1 - hi_f(h));
    return h;
}
__device__ __forceinline__ void mma_bf16(float* d, const uint32_t* a, uint32_t b0, uint32_t b1) {
    asm volatile(
        "mma.sync.aligned.m16n8k16.row.col.f32.bf16.bf16.f32 "
        "{%0,%1,%2,%3}, {%4,%5,%6,%7}, {%8,%9}, {%0,%1,%2,%3};"
        : "+f"(d[0]), "+f"(d[1]), "+f"(d[2]), "+f"(d[3])
        : "r"(a[0]), "r"(a[1]), "r"(a[2]), "r"(a[3]), "r"(b0), "r"(b1));
}

// ---------------------------------------------------------------------------
// Kernel 0: split W=[Wq|Wk|Wv] into bf16 h/l, TRANSPOSED-PACKED: [n][kpair].
// idx -> (n, kpair). Reads hit L1 after first touch (768 KB working set).
// ---------------------------------------------------------------------------
__global__ __launch_bounds__(512) void wsplit(
    const float* __restrict__ Wq, const float* __restrict__ Wk,
    const float* __restrict__ Wv)
{
    int idx = blockIdx.x * 512 + threadIdx.x;   // 0 .. 98303
    int n = idx >> 9, kp = idx & 511;
    const float* col = ((n < 64) ? Wq : (n < 128) ? Wk : Wv) + (n & 63);
    float v0 = col[(2 * kp) * 64];
    float v1 = col[(2 * kp + 1) * 64];
    uint32_t l, h = split_pk(v0, v1, l);
    g_wph[n * 512 + kp] = h;
    g_wpl[n * 512 + kp] = l;
}

// ---------------------------------------------------------------------------
// Kernel 1: fused QKV projection, mma.sync bf16 m16n8k16, 4-term split.
// 256 thr = 8 warps, warp tile 32x48 (wm 2 x wn 4). K-chunks of 32 (2 k16
// steps). A (X) split in-loop; B (W) pre-split packed. Epilogue writes
// Q/K packed bf16-pairs and V transposed bf16 (h/l).
// ---------------------------------------------------------------------------
#define KCH 32
#define NCH (Ee / KCH)            // 32
#define PA 68                     // A pitch (f32)
#define PBP 20                    // B pitch (u32 pairs)
#define QSTG 12032                // u32 per stage: A 4352 + Bh 3840 + Bl 3840
#define QO_BH 4352
#define QO_BL 8192
#define QKV_SMEM_BYTES (2 * QSTG * 4)   // 96256

extern __shared__ float dyn_sm[];

__global__ __launch_bounds__(256, 1) void qkv_mma(
    const float* __restrict__ x,
    const float* __restrict__ bq, const float* __restrict__ bk,
    const float* __restrict__ bv)
{
    uint32_t* su = (uint32_t*)dyn_sm;
    const int tid  = threadIdx.x;
    const int wid  = tid >> 5;
    const int lane = tid & 31;
    const int grp  = lane >> 2;
    const int t4   = lane & 3;
    const int wm   = wid >> 2;        // 0..1 : 32-row slice
    const int wn   = wid & 3;         // 0..3 : 48-col slice
    const int row0 = blockIdx.x * 64;

    const uint32_t sbase = smem_u32(dyn_sm);

    float d[2][6][4];
    #pragma unroll
    for (int f = 0; f < 2; ++f)
        #pragma unroll
        for (int t = 0; t < 6; ++t)
            { d[f][t][0] = 0.f; d[f][t][1] = 0.f; d[f][t][2] = 0.f; d[f][t][3] = 0.f; }

    auto issue = [&](int c, int s) {
        const int k0 = c * KCH;
        const uint32_t st = sbase + (uint32_t)(s * QSTG) * 4u;
        // A: 64 rows x 8 float4 f32
        #pragma unroll
        for (int it = 0; it < 2; ++it) {
            int i = tid + it * 256;
            int r = i >> 3, c4 = i & 7;
            CP_ASYNC16(st + (uint32_t)(r * PA + c4 * 4) * 4u,
                       x + (size_t)(row0 + r) * Ee + k0 + c4 * 4);
        }
        // Bh/Bl packed: 192 n-rows x 16 u32 (4 chunks of 16B) each
        #pragma unroll
        for (int it = 0; it < 6; ++it) {
            int i = tid + it * 256;           // 0..1535
            int arr = i >= 768;
            int j = arr ? i - 768 : i;
            int n = j >> 2, c4 = j & 3;
            const uint32_t* src = (arr ? g_wpl : g_wph) + n * 512 + c * 16 + c4 * 4;
            CP_ASYNC16(st + (uint32_t)((arr ? QO_BL : QO_BH) + n * PBP + c4 * 4) * 4u, src);
        }
        CP_COMMIT();
    };

    issue(0, 0);

    #pragma unroll 1
    for (int c = 0; c < NCH; ++c) {
        const int s = c & 1;
        if (c + 1 < NCH) { issue(c + 1, s ^ 1); CP_WAIT1(); }
        else             { CP_WAIT0(); }
        __syncthreads();

        const float*    A  = dyn_sm + s * QSTG;
        const uint32_t* Bh = su + s * QSTG + QO_BH;
        const uint32_t* Bl = su + s * QSTG + QO_BL;

        #pragma unroll
        for (int kk = 0; kk < 2; ++kk) {
            uint32_t ah[2][4], al[2][4];
            #pragma unroll
            for (int f = 0; f < 2; ++f) {
                const float* ar  = A + (wm * 32 + f * 16 + grp) * PA + 16 * kk;
                const float* ar8 = ar + 8 * PA;
                ah[f][0] = split_pk(ar [2*t4],     ar [2*t4 + 1], al[f][0]);
                ah[f][1] = split_pk(ar8[2*t4],     ar8[2*t4 + 1], al[f][1]);
                ah[f][2] = split_pk(ar [2*t4 + 8], ar [2*t4 + 9], al[f][2]);
                ah[f][3] = split_pk(ar8[2*t4 + 8], ar8[2*t4 + 9], al[f][3]);
            }
            #pragma unroll
            for (int tn = 0; tn < 6; ++tn) {
                const int nrow = (wn * 48 + tn * 8 + grp) * PBP + kk * 8;
                uint32_t bh0 = Bh[nrow + t4];
                uint32_t bh1 = Bh[nrow + t4 + 4];
                uint32_t bl0 = Bl[nrow + t4];
                uint32_t bl1 = Bl[nrow + t4 + 4];
                #pragma unroll
                for (int f = 0; f < 2; ++f) {
                    mma_bf16(d[f][tn], ah[f], bh0, bh1);
                    mma_bf16(d[f][tn], ah[f], bl0, bl1);
                    mma_bf16(d[f][tn], al[f], bh0, bh1);
                    mma_bf16(d[f][tn], al[f], bl0, bl1);
                }
            }
        }
        __syncthreads();
    }

    // epilogue: +bias; Q -> packed x8-scaled bf16 h/l; K -> packed; V -> V^T bf16
    const float* biases[3] = { bq, bk, bv };
    #pragma unroll
    for (int f = 0; f < 2; ++f) {
        const int r_hi = row0 + wm * 32 + f * 16 + grp;
        const int bi = r_hi >> 11, key = r_hi & 2047;
        #pragma unroll
        for (int tn = 0; tn < 6; ++tn) {
            int ng  = wn * 48 + tn * 8 + 2 * t4;
            int mat = ng >> 6, nc = ng & 63;
            float b0 = biases[mat][nc], b1 = biases[mat][nc + 1];
            float v00 = d[f][tn][0] + b0, v01 = d[f][tn][1] + b1;   // row r_hi
            float v10 = d[f][tn][2] + b0, v11 = d[f][tn][3] + b1;   // row r_hi+8
            if (mat == 0) {
                uint32_t l0, l1;
                uint32_t h0 = split_pk(8.f * v00, 8.f * v01, l0);
                uint32_t h1 = split_pk(8.f * v10, 8.f * v11, l1);
                g_qph[(size_t)r_hi * 32 + nc/2]       = h0;
                g_qpl[(size_t)r_hi * 32 + nc/2]       = l0;
                g_qph[(size_t)(r_hi + 8) * 32 + nc/2] = h1;
                g_qpl[(size_t)(r_hi + 8) * 32 + nc/2] = l1;
            } else if (mat == 1) {
                uint32_t l0, l1;
                uint32_t h0 = split_pk(v00, v01, l0);
                uint32_t h1 = split_pk(v10, v11, l1);
                g_kph[(size_t)r_hi * 32 + nc/2]       = h0;
                g_kpl[(size_t)r_hi * 32 + nc/2]       = l0;
                g_kph[(size_t)(r_hi + 8) * 32 + nc/2] = h1;
                g_kpl[(size_t)(r_hi + 8) * 32 + nc/2] = l1;
            } else {
                // V transposed: [bi][dim][key] bf16 h/l
                uint32_t lp, hp;
                size_t base0 = ((size_t)bi * Hh + nc) * Tt;
                size_t base1 = ((size_t)bi * Hh + nc + 1) * Tt;
                hp = split_pk(v00, 0.f, lp);
                g_vth[base0 + key] = (unsigned short)(hp & 0xFFFFu);
                g_vtl[base0 + key] = (unsigned short)(lp & 0xFFFFu);
                hp = split_pk(v01, 0.f, lp);
                g_vth[base1 + key] = (unsigned short)(hp & 0xFFFFu);
                g_vtl[base1 + key] = (unsigned short)(lp & 0xFFFFu);
                hp = split_pk(v10, 0.f, lp);
                g_vth[base0 + key + 8] = (unsigned short)(hp & 0xFFFFu);
                g_vtl[base0 + key + 8] = (unsigned short)(lp & 0xFFFFu);
                hp = split_pk(v11, 0.f, lp);
                g_vth[base1 + key + 8] = (unsigned short)(hp & 0xFFFFu);
                g_vtl[base1 + key + 8] = (unsigned short)(lp & 0xFFFFu);
            }
        }
    }
}

// ---------------------------------------------------------------------------
// Kernel 2: causal flash attention, mma.sync bf16 m16n8k16.
// 256 thr, merged pair streaming (R13 structure). S: 4-term split; PV: 3-term.
// All operands pre-split packed bf16 pairs; V pre-transposed.
// Pitches (u32): Q/K/VT 36, P 12 — conflict-free for the fragment patterns.
// ---------------------------------------------------------------------------
#define KVS   9216                 // u32 per KV stage
#define O_KPH 0
#define O_KPL 2304
#define O_VTH 4608
#define O_VTL 6912
#define O_QPH 18432
#define O_QPL 20736
#define O_P   23040                // 8 warps x (Pph 192 | Ppl 192)
#define O_MS  26112
#define O_LS  26368
#define O_LG  26624
#define PO 67
#define ATTN_SMEM_BYTES (26688 * 4)   // 106752

__global__ __launch_bounds__(256, 1) void attn_mma(float* __restrict__ out)
{
    float*    smf = dyn_sm;
    uint32_t* su  = (uint32_t*)dyn_sm;
    const uint32_t sbase = smem_u32(dyn_sm);
    const int tid  = threadIdx.x;
    const int wid  = tid >> 5;
    const int lane = tid & 31;
    const int grp  = lane >> 2;
    const int t4   = lane & 3;
    const int wm   = wid & 1;
    const int wn   = wid >> 1;
    const int pair = blockIdx.x;
    const int b    = blockIdx.y;

    const int r0 = wm * 16 + grp;

    const int qtA = pair, qtB = 63 - pair;
    const int qbaseA = qtA * 32, qbaseB = qtB * 32;
    const int nktA = qtA / 2 + 1, nktB = qtB / 2 + 1;

    auto issue_kv = [&](int t0, int s) {
        const uint32_t st = sbase + (uint32_t)(s * KVS) * 4u;
        #pragma unroll
        for (int it = 0; it < 4; ++it) {
            int i = tid + it * 256;              // 0..1023
            int arr = (i >= 512);
            int j = arr ? i - 512 : i;
            int r = j >> 3, c = j & 7;
            // K rows (key)
            const uint32_t* ks = (arr ? g_kpl : g_kph)
                               + ((size_t)(b * Tt + t0 * 64 + r)) * 32 + c * 4;
            CP_ASYNC16(st + (uint32_t)((arr ? O_KPL : O_KPH) + r * 36 + c * 4) * 4u, ks);
            // V^T rows (dim)
            const unsigned short* vs = (arr ? g_vtl : g_vth)
                               + ((size_t)(b * Hh + r)) * Tt + t0 * 64 + c * 8;
            CP_ASYNC16(st + (uint32_t)((arr ? O_VTL : O_VTH) + r * 36 + c * 4) * 4u, vs);
        }
        CP_COMMIT();
    };

    // stage Q (both tiles) via cp.async: rows 0..31 = A, 32..63 = B
    #pragma unroll
    for (int it = 0; it < 4; ++it) {
        int i = tid + it * 256;                  // 0..1023
        int arr = (i >= 512);
        int j = arr ? i - 512 : i;
        int r = j >> 3, c = j & 7;
        int gq = (r < 32) ? (qbaseA + r) : (qbaseB + (r - 32));
        const uint32_t* qs = (arr ? g_qpl : g_qph) + ((size_t)(b * Tt + gq)) * 32 + c * 4;
        CP_ASYNC16(sbase + (uint32_t)((arr ? O_QPL : O_QPH) + r * 36 + c * 4) * 4u, qs);
    }
    issue_kv(0, 0);   // commit groups Q + tile0 together

    float OfA[8][4], OfB[8][4];
    #pragma unroll
    for (int nt = 0; nt < 8; ++nt) {
        OfA[nt][0] = 0.f; OfA[nt][1] = 0.f; OfA[nt][2] = 0.f; OfA[nt][3] = 0.f;
        OfB[nt][0] = 0.f; OfB[nt][1] = 0.f; OfB[nt][2] = 0.f; OfB[nt][3] = 0.f;
    }
    float mA0 = -INFINITY, mA1 = -INFINITY, lA0 = 0.f, lA1 = 0.f;
    float mB0 = -INFINITY, mB1 = -INFINITY, lB0 = 0.f, lB1 = 0.f;

    auto tile_compute = [&](int t0, int qoff, int qbase, int nkt,
                            const uint32_t* Kh, const uint32_t* Kl,
                            const uint32_t* Vh, const uint32_t* Vl,
                            float (&Of)[8][4],
                            float& m0, float& m1, float& l0, float& l1) {
        // ---- S = Q.K^T : 4-term bf16, 4 independent acc sets ----
        float shh[8], shl[8], slh[8], sll[8];
        #pragma unroll
        for (int i = 0; i < 8; ++i) { shh[i]=0.f; shl[i]=0.f; slh[i]=0.f; sll[i]=0.f; }

        const uint32_t* qh = su + O_QPH + (qoff + r0) * 36;
        const uint32_t* ql = su + O_QPL + (qoff + r0) * 36;
        #pragma unroll
        for (int kk = 0; kk < 4; ++kk) {
            const int cb = kk * 8;
            uint32_t ah[4], al[4];
            ah[0] = qh[cb + t4];          al[0] = ql[cb + t4];
            ah[1] = qh[8*36 + cb + t4];   al[1] = ql[8*36 + cb + t4];
            ah[2] = qh[cb + t4 + 4];      al[2] = ql[cb + t4 + 4];
            ah[3] = qh[8*36 + cb + t4+4]; al[3] = ql[8*36 + cb + t4 + 4];
            #pragma unroll
            for (int nt = 0; nt < 2; ++nt) {
                const int ro = (wn * 16 + nt * 8 + grp) * 36 + cb;
                uint32_t bh0 = Kh[ro + t4];
                uint32_t bh1 = Kh[ro + t4 + 4];
                uint32_t bl0 = Kl[ro + t4];
                uint32_t bl1 = Kl[ro + t4 + 4];
                mma_bf16(shh + 4*nt, ah, bh0, bh1);
                mma_bf16(shl + 4*nt, ah, bl0, bl1);
                mma_bf16(slh + 4*nt, al, bh0, bh1);
                mma_bf16(sll + 4*nt, al, bl0, bl1);
            }
        }
        float sf[8];
        #pragma unroll
        for (int i = 0; i < 8; ++i) sf[i] = (shh[i] + sll[i]) + (shl[i] + slh[i]);

        // ---- causal mask (last tile of this set only) ----
        if (t0 == nkt - 1) {
            const int kc = t0 * 64 + wn * 16 + 2 * t4;
            const int q0 = qbase + r0, q1 = q0 + 8;
            #pragma unroll
            for (int nt = 0; nt < 2; ++nt) {
                int k0c = kc + nt * 8;
                if (k0c     > q0) sf[4*nt+0] = -INFINITY;
                if (k0c + 1 > q0) sf[4*nt+1] = -INFINITY;
                if (k0c     > q1) sf[4*nt+2] = -INFINITY;
                if (k0c + 1 > q1) sf[4*nt+3] = -INFINITY;
            }
        }

        // ---- online softmax ----
        float rmax0 = fmaxf(fmaxf(sf[0], sf[1]), fmaxf(sf[4], sf[5]));
        float rmax1 = fmaxf(fmaxf(sf[2], sf[3]), fmaxf(sf[6], sf[7]));
        rmax0 = fmaxf(rmax0, __shfl_xor_sync(0xffffffffu, rmax0, 1));
        rmax0 = fmaxf(rmax0, __shfl_xor_sync(0xffffffffu, rmax0, 2));
        rmax1 = fmaxf(rmax1, __shfl_xor_sync(0xffffffffu, rmax1, 1));
        rmax1 = fmaxf(rmax1, __shfl_xor_sync(0xffffffffu, rmax1, 2));

        float mn0 = fmaxf(m0, rmax0), mn1 = fmaxf(m1, rmax1);
        float sm0 = (mn0 == -INFINITY) ? 0.f : mn0;
        float sm1 = (mn1 == -INFINITY) ? 0.f : mn1;
        float corr0 = __expf(m0 - sm0);
        float corr1 = __expf(m1 - sm1);
        m0 = mn0; m1 = mn1;

        float p[8];
        p[0] = __expf(sf[0] - sm0); p[1] = __expf(sf[1] - sm0);
        p[4] = __expf(sf[4] - sm0); p[5] = __expf(sf[5] - sm0);
        p[2] = __expf(sf[2] - sm1); p[3] = __expf(sf[3] - sm1);
        p[6] = __expf(sf[6] - sm1); p[7] = __expf(sf[7] - sm1);

        float rs0 = (p[0] + p[1]) + (p[4] + p[5]);
        float rs1 = (p[2] + p[3]) + (p[6] + p[7]);
        rs0 += __shfl_xor_sync(0xffffffffu, rs0, 1);
        rs0 += __shfl_xor_sync(0xffffffffu, rs0, 2);
        rs1 += __shfl_xor_sync(0xffffffffu, rs1, 1);
        rs1 += __shfl_xor_sync(0xffffffffu, rs1, 2);
        l0 = l0 * corr0 + rs0;
        l1 = l1 * corr1 + rs1;

        #pragma unroll
        for (int nt = 0; nt < 8; ++nt) {
            Of[nt][0] *= corr0; Of[nt][1] *= corr0;
            Of[nt][2] *= corr1; Of[nt][3] *= corr1;
        }

        // ---- stage P split packed (h & l) ----
        uint32_t* Pph = su + O_P + wid * 384;
        uint32_t* Ppl = Pph + 192;
        {
            uint32_t lp;
            Pph[grp * 12 + t4]           = split_pk(p[0], p[1], lp); Ppl[grp * 12 + t4]           = lp;
            Pph[grp * 12 + t4 + 4]       = split_pk(p[4], p[5], lp); Ppl[grp * 12 + t4 + 4]       = lp;
            Pph[(grp + 8) * 12 + t4]     = split_pk(p[2], p[3], lp); Ppl[(grp + 8) * 12 + t4]     = lp;
            Pph[(grp + 8) * 12 + t4 + 4] = split_pk(p[6], p[7], lp); Ppl[(grp + 8) * 12 + t4 + 4] = lp;
        }
        __syncwarp();

        // ---- O += 3-term P.V (single k16 step covers the 16-key slice) ----
        uint32_t ph[4], pl[4];
        ph[0] = Pph[grp * 12 + t4];           pl[0] = Ppl[grp * 12 + t4];
        ph[1] = Pph[(grp + 8) * 12 + t4];     pl[1] = Ppl[(grp + 8) * 12 + t4];
        ph[2] = Pph[grp * 12 + t4 + 4];       pl[2] = Ppl[grp * 12 + t4 + 4];
        ph[3] = Pph[(grp + 8) * 12 + t4 + 4]; pl[3] = Ppl[(grp + 8) * 12 + t4 + 4];

        #pragma unroll
        for (int nt = 0; nt < 8; ++nt) {
            const int vr = (nt * 8 + grp) * 36 + wn * 8;
            uint32_t vh0 = Vh[vr + t4];
            uint32_t vh1 = Vh[vr + t4 + 4];
            uint32_t vl0 = Vl[vr + t4];
            uint32_t vl1 = Vl[vr + t4 + 4];
            mma_bf16(Of[nt], ph, vh0, vh1);
            mma_bf16(Of[nt], ph, vl0, vl1);
            mma_bf16(Of[nt], pl, vh0, vh1);
        }
        __syncwarp();
    };

    // ---- single merged K/V stream ----
    #pragma unroll 1
    for (int t0 = 0; t0 < nktB; ++t0) {
        const int s = t0 & 1;
        __syncthreads();
        if (t0 + 1 < nktB) { issue_kv(t0 + 1, s ^ 1); CP_WAIT1(); }
        else               { CP_WAIT0(); }
        __syncthreads();

        const uint32_t* Kh = su + s * KVS + O_KPH;
        const uint32_t* Kl = su + s * KVS + O_KPL;
        const uint32_t* Vh = su + s * KVS + O_VTH;
        const uint32_t* Vl = su + s * KVS + O_VTL;

        tile_compute(t0, 32, qbaseB, nktB, Kh, Kl, Vh, Vl, OfB, mB0, mB1, lB0, lB1);
        if (t0 < nktA)
            tile_compute(t0, 0, qbaseA, nktA, Kh, Kl, Vh, Vl, OfA, mA0, mA1, lA0, lA1);
    }

    // ---- merge 4 wn-slices for both sets ----
    __syncthreads();
    if (t4 == 0) {
        int si = (wm * 4 + wn) * 16 + grp;
        smf[O_MS + si]           = mA0; smf[O_MS + si + 8]       = mA1;
        smf[O_LS + si]           = lA0; smf[O_LS + si + 8]       = lA1;
        smf[O_MS + 128 + si]     = mB0; smf[O_MS + 128 + si + 8] = mB1;
        smf[O_LS + 128 + si]     = lB0; smf[O_LS + 128 + si + 8] = lB1;
    }
    __syncthreads();

    float wA0, wA1, wB0, wB1;
    {
        float mg0 = -INFINITY, mg1 = -INFINITY;
        #pragma unroll
        for (int w = 0; w < 4; ++w) {
            mg0 = fmaxf(mg0, smf[O_MS + (wm * 4 + w) * 16 + grp]);
            mg1 = fmaxf(mg1, smf[O_MS + (wm * 4 + w) * 16 + grp + 8]);
        }
        float lg0 = 0.f, lg1 = 0.f;
        #pragma unroll
        for (int w = 0; w < 4; ++w) {
            lg0 += smf[O_LS + (wm * 4 + w) * 16 + grp]     * __expf(smf[O_MS + (wm * 4 + w) * 16 + grp]     - mg0);
            lg1 += smf[O_LS + (wm * 4 + w) * 16 + grp + 8] * __expf(smf[O_MS + (wm * 4 + w) * 16 + grp + 8] - mg1);
        }
        wA0 = __expf(mA0 - mg0);
        wA1 = __expf(mA1 - mg1);
        if (wn == 0 && t4 == 0) { smf[O_LG + r0] = lg0; smf[O_LG + r0 + 8] = lg1; }
    }
    {
        float mg0 = -INFINITY, mg1 = -INFINITY;
        #pragma unroll
        for (int w = 0; w < 4; ++w) {
            mg0 = fmaxf(mg0, smf[O_MS + 128 + (wm * 4 + w) * 16 + grp]);
            mg1 = fmaxf(mg1, smf[O_MS + 128 + (wm * 4 + w) * 16 + grp + 8]);
        }
        float lg0 = 0.f, lg1 = 0.f;
        #pragma unroll
        for (int w = 0; w < 4; ++w) {
            lg0 += smf[O_LS + 128 + (wm * 4 + w) * 16 + grp]     * __expf(smf[O_MS + 128 + (wm * 4 + w) * 16 + grp]     - mg0);
            lg1 += smf[O_LS + 128 + (wm * 4 + w) * 16 + grp + 8] * __expf(smf[O_MS + 128 + (wm * 4 + w) * 16 + grp + 8] - mg1);
        }
        wB0 = __expf(mB0 - mg0);
        wB1 = __expf(mB1 - mg1);
        if (wn == 0 && t4 == 0) { smf[O_LG + 32 + r0] = lg0; smf[O_LG + 32 + r0 + 8] = lg1; }
    }
    #pragma unroll
    for (int nt = 0; nt < 8; ++nt) {
        OfA[nt][0] *= wA0; OfA[nt][1] *= wA0;
        OfA[nt][2] *= wA1; OfA[nt][3] *= wA1;
        OfB[nt][0] *= wB0; OfB[nt][1] *= wB0;
        OfB[nt][2] *= wB1; OfB[nt][3] *= wB1;
    }

    float* accA = smf;            // aliases KV stage 0 (free now)
    float* accB = smf + KVS;      // aliases KV stage 1
    #pragma unroll 1
    for (int r = 0; r < 4; ++r) {
        __syncthreads();
        if (wn == r) {
            #pragma unroll
            for (int nt = 0; nt < 8; ++nt) {
                int a0 = r0 * PO + nt * 8 + 2 * t4;
                int a1 = (r0 + 8) * PO + nt * 8 + 2 * t4;
                if (r == 0) {
                    accA[a0] = OfA[nt][0]; accA[a0 + 1] = OfA[nt][1];
                    accA[a1] = OfA[nt][2]; accA[a1 + 1] = OfA[nt][3];
                    accB[a0] = OfB[nt][0]; accB[a0 + 1] = OfB[nt][1];
                    accB[a1] = OfB[nt][2]; accB[a1 + 1] = OfB[nt][3];
                } else {
                    accA[a0] += OfA[nt][0]; accA[a0 + 1] += OfA[nt][1];
                    accA[a1] += OfA[nt][2]; accA[a1 + 1] += OfA[nt][3];
                    accB[a0] += OfB[nt][0]; accB[a0 + 1] += OfB[nt][1];
                    accB[a1] += OfB[nt][2]; accB[a1 + 1] += OfB[nt][3];
                }
            }
        }
    }
    __syncthreads();

    const size_t boff = (size_t)(b * Tt) * Hh;
    float* opA = out + boff + (size_t)qbaseA * Hh;
    float* opB = out + boff + (size_t)qbaseB * Hh;
    #pragma unroll
    for (int it = 0; it < 8; ++it) {
        int i = tid + it * 256;
        int r = i >> 6, dd = i & 63;
        opA[i] = accA[r * PO + dd] * __fdividef(1.0f, smf[O_LG + r]);
        opB[i] = accB[r * PO + dd] * __fdividef(1.0f, smf[O_LG + 32 + r]);
    }
}

extern "C" void kernel_launch(void* const* d_in, const int* in_sizes, int n_in,
                              void* d_out, int out_size)
{
    const float* x  = (const float*)d_in[0];
    const float* Wq = (const float*)d_in[1];
    const float* bq = (const float*)d_in[2];
    const float* Wk = (const float*)d_in[3];
    const float* bk = (const float*)d_in[4];
    const float* Wv = (const float*)d_in[5];
    const float* bv = (const float*)d_in[6];
    float* out = (float*)d_out;

    cudaFuncSetAttribute(qkv_mma, cudaFuncAttributeMaxDynamicSharedMemorySize,
                         QKV_SMEM_BYTES);
    cudaFuncSetAttribute(attn_mma, cudaFuncAttributeMaxDynamicSharedMemorySize,
                         ATTN_SMEM_BYTES);

    wsplit<<<192, 512>>>(Wq, Wk, Wv);
    qkv_mma<<<128, 256, QKV_SMEM_BYTES>>>(x, bq, bk, bv);
    attn_mma<<<dim3(32, 4), 256, ATTN_SMEM_BYTES>>>(out);
}

// round 17
// speedup vs baseline: 1.3357x; 1.0275x over previous
#include <cuda_runtime.h>
#include <cuda_bf16.h>
#include <math.h>
#include <cstdint>

#define Bb 4
#define Tt 2048
#define Ee 1024
#define Hh 64
#define ROWS (Bb*Tt)

// packed bf16-pair operands (u32 = 2 bf16)
__device__ uint32_t       g_qph[ROWS*32], g_qpl[ROWS*32];   // Q (x8 folded), packed along dim
__device__ uint32_t       g_kph[ROWS*32], g_kpl[ROWS*32];   // K packed along dim
__device__ unsigned short g_vth[ROWS*Hh], g_vtl[ROWS*Hh];   // V^T  [b][dim][key]
__device__ uint32_t       g_wph[192*512], g_wpl[192*512];   // W^T packed along k: [n][kpair]

// ---------------------------------------------------------------------------
// Helpers
// ---------------------------------------------------------------------------
__device__ __forceinline__ uint32_t smem_u32(const void* p) {
    uint32_t a;
    asm("{ .reg .u64 t; cvta.to.shared.u64 t, %1; cvt.u32.u64 %0, t; }" : "=r"(a) : "l"(p));
    return a;
}
#define CP_ASYNC16(dst_u32, src_ptr) \
    asm volatile("cp.async.cg.shared.global [%0], [%1], 16;" :: "r"(dst_u32), "l"(src_ptr))
#define CP_COMMIT() asm volatile("cp.async.commit_group;" ::: "memory")
#define CP_WAIT0()  asm volatile("cp.async.wait_group 0;" ::: "memory")
#define CP_WAIT1()  asm volatile("cp.async.wait_group 1;" ::: "memory")

__device__ __forceinline__ uint32_t pk_bf16(float lo, float hi) {
    uint32_t r;
    asm("cvt.rn.bf16x2.f32 %0, %1, %2;" : "=r"(r) : "f"(hi), "f"(lo));
    return r;
}
__device__ __forceinline__ float lo_f(uint32_t p) { return __uint_as_float(p << 16); }
__device__ __forceinline__ float hi_f(uint32_t p) { return __uint_as_float(p & 0xFFFF0000u); }
// split (v0,v1) into high-pack (returned) and low-pack (residuals)
__device__ __forceinline__ uint32_t split_pk(float v0, float v1, uint32_t& lpk) {
    uint32_t h = pk_bf16(v0, v1);
    lpk = pk_bf16(v0 - lo_f(h), v1 - hi_f(h));
    return h;
}
__device__ __forceinline__ void mma_bf16(float* d, const uint32_t* a, uint32_t b0, uint32_t b1) {
    asm volatile(
        "mma.sync.aligned.m16n8k16.row.col.f32.bf16.bf16.f32 "
        "{%0,%1,%2,%3}, {%4,%5,%6,%7}, {%8,%9}, {%0,%1,%2,%3};"
        : "+f"(d[0]), "+f"(d[1]), "+f"(d[2]), "+f"(d[3])
        : "r"(a[0]), "r"(a[1]), "r"(a[2]), "r"(a[3]), "r"(b0), "r"(b1));
}

// ---------------------------------------------------------------------------
// Kernel 0: split W=[Wq|Wk|Wv] into bf16 h/l, TRANSPOSED-PACKED: [n][kpair].
// ---------------------------------------------------------------------------
__global__ __launch_bounds__(512) void wsplit(
    const float* __restrict__ Wq, const float* __restrict__ Wk,
    const float* __restrict__ Wv)
{
    int idx = blockIdx.x * 512 + threadIdx.x;   // 0 .. 98303
    int n = idx >> 9, kp = idx & 511;
    const float* col = ((n < 64) ? Wq : (n < 128) ? Wk : Wv) + (n & 63);
    float v0 = col[(2 * kp) * 64];
    float v1 = col[(2 * kp + 1) * 64];
    uint32_t l, h = split_pk(v0, v1, l);
    g_wph[n * 512 + kp] = h;
    g_wpl[n * 512 + kp] = l;
}

// ---------------------------------------------------------------------------
// Kernel 1: fused QKV projection, mma.sync bf16 m16n8k16, 3-term split
// (hh + hl + lh; ll dropped ~2^-18 rel). 256 thr, warp tile 32x48.
// ---------------------------------------------------------------------------
#define KCH 32
#define NCH (Ee / KCH)            // 32
#define PA 68                     // A pitch (f32)
#define PBP 20                    // B pitch (u32 pairs)
#define QSTG 12032                // u32 per stage: A 4352 + Bh 3840 + Bl 3840
#define QO_BH 4352
#define QO_BL 8192
#define QKV_SMEM_BYTES (2 * QSTG * 4)   // 96256

extern __shared__ float dyn_sm[];

__global__ __launch_bounds__(256, 1) void qkv_mma(
    const float* __restrict__ x,
    const float* __restrict__ bq, const float* __restrict__ bk,
    const float* __restrict__ bv)
{
    uint32_t* su = (uint32_t*)dyn_sm;
    const int tid  = threadIdx.x;
    const int wid  = tid >> 5;
    const int lane = tid & 31;
    const int grp  = lane >> 2;
    const int t4   = lane & 3;
    const int wm   = wid >> 2;        // 0..1 : 32-row slice
    const int wn   = wid & 3;         // 0..3 : 48-col slice
    const int row0 = blockIdx.x * 64;

    const uint32_t sbase = smem_u32(dyn_sm);

    float d[2][6][4];
    #pragma unroll
    for (int f = 0; f < 2; ++f)
        #pragma unroll
        for (int t = 0; t < 6; ++t)
            { d[f][t][0] = 0.f; d[f][t][1] = 0.f; d[f][t][2] = 0.f; d[f][t][3] = 0.f; }

    auto issue = [&](int c, int s) {
        const int k0 = c * KCH;
        const uint32_t st = sbase + (uint32_t)(s * QSTG) * 4u;
        // A: 64 rows x 8 float4 f32
        #pragma unroll
        for (int it = 0; it < 2; ++it) {
            int i = tid + it * 256;
            int r = i >> 3, c4 = i & 7;
            CP_ASYNC16(st + (uint32_t)(r * PA + c4 * 4) * 4u,
                       x + (size_t)(row0 + r) * Ee + k0 + c4 * 4);
        }
        // Bh/Bl packed: 192 n-rows x 16 u32 (4 chunks of 16B) each
        #pragma unroll
        for (int it = 0; it < 6; ++it) {
            int i = tid + it * 256;           // 0..1535
            int arr = i >= 768;
            int j = arr ? i - 768 : i;
            int n = j >> 2, c4 = j & 3;
            const uint32_t* src = (arr ? g_wpl : g_wph) + n * 512 + c * 16 + c4 * 4;
            CP_ASYNC16(st + (uint32_t)((arr ? QO_BL : QO_BH) + n * PBP + c4 * 4) * 4u, src);
        }
        CP_COMMIT();
    };

    issue(0, 0);

    #pragma unroll 1
    for (int c = 0; c < NCH; ++c) {
        const int s = c & 1;
        if (c + 1 < NCH) { issue(c + 1, s ^ 1); CP_WAIT1(); }
        else             { CP_WAIT0(); }
        __syncthreads();

        const float*    A  = dyn_sm + s * QSTG;
        const uint32_t* Bh = su + s * QSTG + QO_BH;
        const uint32_t* Bl = su + s * QSTG + QO_BL;

        #pragma unroll
        for (int kk = 0; kk < 2; ++kk) {
            uint32_t ah[2][4], al[2][4];
            #pragma unroll
            for (int f = 0; f < 2; ++f) {
                const float* ar  = A + (wm * 32 + f * 16 + grp) * PA + 16 * kk;
                const float* ar8 = ar + 8 * PA;
                ah[f][0] = split_pk(ar [2*t4],     ar [2*t4 + 1], al[f][0]);
                ah[f][1] = split_pk(ar8[2*t4],     ar8[2*t4 + 1], al[f][1]);
                ah[f][2] = split_pk(ar [2*t4 + 8], ar [2*t4 + 9], al[f][2]);
                ah[f][3] = split_pk(ar8[2*t4 + 8], ar8[2*t4 + 9], al[f][3]);
            }
            #pragma unroll
            for (int tn = 0; tn < 6; ++tn) {
                const int nrow = (wn * 48 + tn * 8 + grp) * PBP + kk * 8;
                uint32_t bh0 = Bh[nrow + t4];
                uint32_t bh1 = Bh[nrow + t4 + 4];
                uint32_t bl0 = Bl[nrow + t4];
                uint32_t bl1 = Bl[nrow + t4 + 4];
                #pragma unroll
                for (int f = 0; f < 2; ++f) {
                    mma_bf16(d[f][tn], ah[f], bh0, bh1);
                    mma_bf16(d[f][tn], ah[f], bl0, bl1);
                    mma_bf16(d[f][tn], al[f], bh0, bh1);
                }
            }
        }
        __syncthreads();
    }

    // epilogue: +bias; Q -> packed x8-scaled bf16 h/l; K -> packed; V -> V^T bf16
    const float* biases[3] = { bq, bk, bv };
    #pragma unroll
    for (int f = 0; f < 2; ++f) {
        const int r_hi = row0 + wm * 32 + f * 16 + grp;
        const int bi = r_hi >> 11, key = r_hi & 2047;
        #pragma unroll
        for (int tn = 0; tn < 6; ++tn) {
            int ng  = wn * 48 + tn * 8 + 2 * t4;
            int mat = ng >> 6, nc = ng & 63;
            float b0 = biases[mat][nc], b1 = biases[mat][nc + 1];
            float v00 = d[f][tn][0] + b0, v01 = d[f][tn][1] + b1;   // row r_hi
            float v10 = d[f][tn][2] + b0, v11 = d[f][tn][3] + b1;   // row r_hi+8
            if (mat == 0) {
                uint32_t l0, l1;
                uint32_t h0 = split_pk(8.f * v00, 8.f * v01, l0);
                uint32_t h1 = split_pk(8.f * v10, 8.f * v11, l1);
                g_qph[(size_t)r_hi * 32 + nc/2]       = h0;
                g_qpl[(size_t)r_hi * 32 + nc/2]       = l0;
                g_qph[(size_t)(r_hi + 8) * 32 + nc/2] = h1;
                g_qpl[(size_t)(r_hi + 8) * 32 + nc/2] = l1;
            } else if (mat == 1) {
                uint32_t l0, l1;
                uint32_t h0 = split_pk(v00, v01, l0);
                uint32_t h1 = split_pk(v10, v11, l1);
                g_kph[(size_t)r_hi * 32 + nc/2]       = h0;
                g_kpl[(size_t)r_hi * 32 + nc/2]       = l0;
                g_kph[(size_t)(r_hi + 8) * 32 + nc/2] = h1;
                g_kpl[(size_t)(r_hi + 8) * 32 + nc/2] = l1;
            } else {
                // V transposed: [bi][dim][key] bf16 h/l
                uint32_t lp, hp;
                size_t base0 = ((size_t)bi * Hh + nc) * Tt;
                size_t base1 = ((size_t)bi * Hh + nc + 1) * Tt;
                hp = split_pk(v00, 0.f, lp);
                g_vth[base0 + key] = (unsigned short)(hp & 0xFFFFu);
                g_vtl[base0 + key] = (unsigned short)(lp & 0xFFFFu);
                hp = split_pk(v01, 0.f, lp);
                g_vth[base1 + key] = (unsigned short)(hp & 0xFFFFu);
                g_vtl[base1 + key] = (unsigned short)(lp & 0xFFFFu);
                hp = split_pk(v10, 0.f, lp);
                g_vth[base0 + key + 8] = (unsigned short)(hp & 0xFFFFu);
                g_vtl[base0 + key + 8] = (unsigned short)(lp & 0xFFFFu);
                hp = split_pk(v11, 0.f, lp);
                g_vth[base1 + key + 8] = (unsigned short)(hp & 0xFFFFu);
                g_vtl[base1 + key + 8] = (unsigned short)(lp & 0xFFFFu);
            }
        }
    }
}

// ---------------------------------------------------------------------------
// Kernel 2: causal flash attention, mma.sync bf16 m16n8k16.
// S: 3-term split (ll dropped); PV: 3-term. Merged pair streaming.
// ---------------------------------------------------------------------------
#define KVS   9216                 // u32 per KV stage
#define O_KPH 0
#define O_KPL 2304
#define O_VTH 4608
#define O_VTL 6912
#define O_QPH 18432
#define O_QPL 20736
#define O_P   23040                // 8 warps x (Pph 192 | Ppl 192)
#define O_MS  26112
#define O_LS  26368
#define O_LG  26624
#define PO 67
#define ATTN_SMEM_BYTES (26688 * 4)   // 106752

__global__ __launch_bounds__(256, 1) void attn_mma(float* __restrict__ out)
{
    float*    smf = dyn_sm;
    uint32_t* su  = (uint32_t*)dyn_sm;
    const uint32_t sbase = smem_u32(dyn_sm);
    const int tid  = threadIdx.x;
    const int wid  = tid >> 5;
    const int lane = tid & 31;
    const int grp  = lane >> 2;
    const int t4   = lane & 3;
    const int wm   = wid & 1;
    const int wn   = wid >> 1;
    const int pair = blockIdx.x;
    const int b    = blockIdx.y;

    const int r0 = wm * 16 + grp;

    const int qtA = pair, qtB = 63 - pair;
    const int qbaseA = qtA * 32, qbaseB = qtB * 32;
    const int nktA = qtA / 2 + 1, nktB = qtB / 2 + 1;

    auto issue_kv = [&](int t0, int s) {
        const uint32_t st = sbase + (uint32_t)(s * KVS) * 4u;
        #pragma unroll
        for (int it = 0; it < 4; ++it) {
            int i = tid + it * 256;              // 0..1023
            int arr = (i >= 512);
            int j = arr ? i - 512 : i;
            int r = j >> 3, c = j & 7;
            const uint32_t* ks = (arr ? g_kpl : g_kph)
                               + ((size_t)(b * Tt + t0 * 64 + r)) * 32 + c * 4;
            CP_ASYNC16(st + (uint32_t)((arr ? O_KPL : O_KPH) + r * 36 + c * 4) * 4u, ks);
            const unsigned short* vs = (arr ? g_vtl : g_vth)
                               + ((size_t)(b * Hh + r)) * Tt + t0 * 64 + c * 8;
            CP_ASYNC16(st + (uint32_t)((arr ? O_VTL : O_VTH) + r * 36 + c * 4) * 4u, vs);
        }
        CP_COMMIT();
    };

    // stage Q (both tiles) via cp.async: rows 0..31 = A, 32..63 = B
    #pragma unroll
    for (int it = 0; it < 4; ++it) {
        int i = tid + it * 256;                  // 0..1023
        int arr = (i >= 512);
        int j = arr ? i - 512 : i;
        int r = j >> 3, c = j & 7;
        int gq = (r < 32) ? (qbaseA + r) : (qbaseB + (r - 32));
        const uint32_t* qs = (arr ? g_qpl : g_qph) + ((size_t)(b * Tt + gq)) * 32 + c * 4;
        CP_ASYNC16(sbase + (uint32_t)((arr ? O_QPL : O_QPH) + r * 36 + c * 4) * 4u, qs);
    }
    issue_kv(0, 0);   // commit groups Q + tile0 together

    float OfA[8][4], OfB[8][4];
    #pragma unroll
    for (int nt = 0; nt < 8; ++nt) {
        OfA[nt][0] = 0.f; OfA[nt][1] = 0.f; OfA[nt][2] = 0.f; OfA[nt][3] = 0.f;
        OfB[nt][0] = 0.f; OfB[nt][1] = 0.f; OfB[nt][2] = 0.f; OfB[nt][3] = 0.f;
    }
    float mA0 = -INFINITY, mA1 = -INFINITY, lA0 = 0.f, lA1 = 0.f;
    float mB0 = -INFINITY, mB1 = -INFINITY, lB0 = 0.f, lB1 = 0.f;

    auto tile_compute = [&](int t0, int qoff, int qbase, int nkt,
                            const uint32_t* Kh, const uint32_t* Kl,
                            const uint32_t* Vh, const uint32_t* Vl,
                            float (&Of)[8][4],
                            float& m0, float& m1, float& l0, float& l1) {
        // ---- S = Q.K^T : 3-term bf16 (hh + hl + lh) ----
        float shh[8], shl[8], slh[8];
        #pragma unroll
        for (int i = 0; i < 8; ++i) { shh[i]=0.f; shl[i]=0.f; slh[i]=0.f; }

        const uint32_t* qh = su + O_QPH + (qoff + r0) * 36;
        const uint32_t* ql = su + O_QPL + (qoff + r0) * 36;
        #pragma unroll
        for (int kk = 0; kk < 4; ++kk) {
            const int cb = kk * 8;
            uint32_t ah[4], al[4];
            ah[0] = qh[cb + t4];          al[0] = ql[cb + t4];
            ah[1] = qh[8*36 + cb + t4];   al[1] = ql[8*36 + cb + t4];
            ah[2] = qh[cb + t4 + 4];      al[2] = ql[cb + t4 + 4];
            ah[3] = qh[8*36 + cb + t4+4]; al[3] = ql[8*36 + cb + t4 + 4];
            #pragma unroll
            for (int nt = 0; nt < 2; ++nt) {
                const int ro = (wn * 16 + nt * 8 + grp) * 36 + cb;
                uint32_t bh0 = Kh[ro + t4];
                uint32_t bh1 = Kh[ro + t4 + 4];
                uint32_t bl0 = Kl[ro + t4];
                uint32_t bl1 = Kl[ro + t4 + 4];
                mma_bf16(shh + 4*nt, ah, bh0, bh1);
                mma_bf16(shl + 4*nt, ah, bl0, bl1);
                mma_bf16(slh + 4*nt, al, bh0, bh1);
            }
        }
        float sf[8];
        #pragma unroll
        for (int i = 0; i < 8; ++i) sf[i] = shh[i] + (shl[i] + slh[i]);

        // ---- causal mask (last tile of this set only) ----
        if (t0 == nkt - 1) {
            const int kc = t0 * 64 + wn * 16 + 2 * t4;
            const int q0 = qbase + r0, q1 = q0 + 8;
            #pragma unroll
            for (int nt = 0; nt < 2; ++nt) {
                int k0c = kc + nt * 8;
                if (k0c     > q0) sf[4*nt+0] = -INFINITY;
                if (k0c + 1 > q0) sf[4*nt+1] = -INFINITY;
                if (k0c     > q1) sf[4*nt+2] = -INFINITY;
                if (k0c + 1 > q1) sf[4*nt+3] = -INFINITY;
            }
        }

        // ---- online softmax ----
        float rmax0 = fmaxf(fmaxf(sf[0], sf[1]), fmaxf(sf[4], sf[5]));
        float rmax1 = fmaxf(fmaxf(sf[2], sf[3]), fmaxf(sf[6], sf[7]));
        rmax0 = fmaxf(rmax0, __shfl_xor_sync(0xffffffffu, rmax0, 1));
        rmax0 = fmaxf(rmax0, __shfl_xor_sync(0xffffffffu, rmax0, 2));
        rmax1 = fmaxf(rmax1, __shfl_xor_sync(0xffffffffu, rmax1, 1));
        rmax1 = fmaxf(rmax1, __shfl_xor_sync(0xffffffffu, rmax1, 2));

        float mn0 = fmaxf(m0, rmax0), mn1 = fmaxf(m1, rmax1);
        float sm0 = (mn0 == -INFINITY) ? 0.f : mn0;
        float sm1 = (mn1 == -INFINITY) ? 0.f : mn1;
        float corr0 = __expf(m0 - sm0);
        float corr1 = __expf(m1 - sm1);
        m0 = mn0; m1 = mn1;

        float p[8];
        p[0] = __expf(sf[0] - sm0); p[1] = __expf(sf[1] - sm0);
        p[4] = __expf(sf[4] - sm0); p[5] = __expf(sf[5] - sm0);
        p[2] = __expf(sf[2] - sm1); p[3] = __expf(sf[3] - sm1);
        p[6] = __expf(sf[6] - sm1); p[7] = __expf(sf[7] - sm1);

        float rs0 = (p[0] + p[1]) + (p[4] + p[5]);
        float rs1 = (p[2] + p[3]) + (p[6] + p[7]);
        rs0 += __shfl_xor_sync(0xffffffffu, rs0, 1);
        rs0 += __shfl_xor_sync(0xffffffffu, rs0, 2);
        rs1 += __shfl_xor_sync(0xffffffffu, rs1, 1);
        rs1 += __shfl_xor_sync(0xffffffffu, rs1, 2);
        l0 = l0 * corr0 + rs0;
        l1 = l1 * corr1 + rs1;

        #pragma unroll
        for (int nt = 0; nt < 8; ++nt) {
            Of[nt][0] *= corr0; Of[nt][1] *= corr0;
            Of[nt][2] *= corr1; Of[nt][3] *= corr1;
        }

        // ---- stage P split packed (h & l) ----
        uint32_t* Pph = su + O_P + wid * 384;
        uint32_t* Ppl = Pph + 192;
        {
            uint32_t lp;
            Pph[grp * 12 + t4]           = split_pk(p[0], p[1], lp); Ppl[grp * 12 + t4]           = lp;
            Pph[grp * 12 + t4 + 4]       = split_pk(p[4], p[5], lp); Ppl[grp * 12 + t4 + 4]       = lp;
            Pph[(grp + 8) * 12 + t4]     = split_pk(p[2], p[3], lp); Ppl[(grp + 8) * 12 + t4]     = lp;
            Pph[(grp + 8) * 12 + t4 + 4] = split_pk(p[6], p[7], lp); Ppl[(grp + 8) * 12 + t4 + 4] = lp;
        }
        __syncwarp();

        // ---- O += 3-term P.V (single k16 step covers the 16-key slice) ----
        uint32_t ph[4], pl[4];
        ph[0] = Pph[grp * 12 + t4];           pl[0] = Ppl[grp * 12 + t4];
        ph[1] = Pph[(grp + 8) * 12 + t4];     pl[1] = Ppl[(grp + 8) * 12 + t4];
        ph[2] = Pph[grp * 12 + t4 + 4];       pl[2] = Ppl[grp * 12 + t4 + 4];
        ph[3] = Pph[(grp + 8) * 12 + t4 + 4]; pl[3] = Ppl[(grp + 8) * 12 + t4 + 4];

        #pragma unroll
        for (int nt = 0; nt < 8; ++nt) {
            const int vr = (nt * 8 + grp) * 36 + wn * 8;
            uint32_t vh0 = Vh[vr + t4];
            uint32_t vh1 = Vh[vr + t4 + 4];
            uint32_t vl0 = Vl[vr + t4];
            uint32_t vl1 = Vl[vr + t4 + 4];
            mma_bf16(Of[nt], ph, vh0, vh1);
            mma_bf16(Of[nt], ph, vl0, vl1);
            mma_bf16(Of[nt], pl, vh0, vh1);
        }
        __syncwarp();
    };

    // ---- single merged K/V stream ----
    #pragma unroll 1
    for (int t0 = 0; t0 < nktB; ++t0) {
        const int s = t0 & 1;
        __syncthreads();
        if (t0 + 1 < nktB) { issue_kv(t0 + 1, s ^ 1); CP_WAIT1(); }
        else               { CP_WAIT0(); }
        __syncthreads();

        const uint32_t* Kh = su + s * KVS + O_KPH;
        const uint32_t* Kl = su + s * KVS + O_KPL;
        const uint32_t* Vh = su + s * KVS + O_VTH;
        const uint32_t* Vl = su + s * KVS + O_VTL;

        tile_compute(t0, 32, qbaseB, nktB, Kh, Kl, Vh, Vl, OfB, mB0, mB1, lB0, lB1);
        if (t0 < nktA)
            tile_compute(t0, 0, qbaseA, nktA, Kh, Kl, Vh, Vl, OfA, mA0, mA1, lA0, lA1);
    }

    // ---- merge 4 wn-slices for both sets ----
    __syncthreads();
    if (t4 == 0) {
        int si = (wm * 4 + wn) * 16 + grp;
        smf[O_MS + si]           = mA0; smf[O_MS + si + 8]       = mA1;
        smf[O_LS + si]           = lA0; smf[O_LS + si + 8]       = lA1;
        smf[O_MS + 128 + si]     = mB0; smf[O_MS + 128 + si + 8] = mB1;
        smf[O_LS + 128 + si]     = lB0; smf[O_LS + 128 + si + 8] = lB1;
    }
    __syncthreads();

    float wA0, wA1, wB0, wB1;
    {
        float mg0 = -INFINITY, mg1 = -INFINITY;
        #pragma unroll
        for (int w = 0; w < 4; ++w) {
            mg0 = fmaxf(mg0, smf[O_MS + (wm * 4 + w) * 16 + grp]);
            mg1 = fmaxf(mg1, smf[O_MS + (wm * 4 + w) * 16 + grp + 8]);
        }
        float lg0 = 0.f, lg1 = 0.f;
        #pragma unroll
        for (int w = 0; w < 4; ++w) {
            lg0 += smf[O_LS + (wm * 4 + w) * 16 + grp]     * __expf(smf[O_MS + (wm * 4 + w) * 16 + grp]     - mg0);
            lg1 += smf[O_LS + (wm * 4 + w) * 16 + grp + 8] * __expf(smf[O_MS + (wm * 4 + w) * 16 + grp + 8] - mg1);
        }
        wA0 = __expf(mA0 - mg0);
        wA1 = __expf(mA1 - mg1);
        if (wn == 0 && t4 == 0) { smf[O_LG + r0] = lg0; smf[O_LG + r0 + 8] = lg1; }
    }
    {
        float mg0 = -INFINITY, mg1 = -INFINITY;
        #pragma unroll
        for (int w = 0; w < 4; ++w) {
            mg0 = fmaxf(mg0, smf[O_MS + 128 + (wm * 4 + w) * 16 + grp]);
            mg1 = fmaxf(mg1, smf[O_MS + 128 + (wm * 4 + w) * 16 + grp + 8]);
        }
        float lg0 = 0.f, lg1 = 0.f;
        #pragma unroll
        for (int w = 0; w < 4; ++w) {
            lg0 += smf[O_LS + 128 + (wm * 4 + w) * 16 + grp]     * __expf(smf[O_MS + 128 + (wm * 4 + w) * 16 + grp]     - mg0);
            lg1 += smf[O_LS + 128 + (wm * 4 + w) * 16 + grp + 8] * __expf(smf[O_MS + 128 + (wm * 4 + w) * 16 + grp + 8] - mg1);
        }
        wB0 = __expf(mB0 - mg0);
        wB1 = __expf(mB1 - mg1);
        if (wn == 0 && t4 == 0) { smf[O_LG + 32 + r0] = lg0; smf[O_LG + 32 + r0 + 8] = lg1; }
    }
    #pragma unroll
    for (int nt = 0; nt < 8; ++nt) {
        OfA[nt][0] *= wA0; OfA[nt][1] *= wA0;
        OfA[nt][2] *= wA1; OfA[nt][3] *= wA1;
        OfB[nt][0] *= wB0; OfB[nt][1] *= wB0;
        OfB[nt][2] *= wB1; OfB[nt][3] *= wB1;
    }

    float* accA = smf;            // aliases KV stage 0 (free now)
    float* accB = smf + KVS;      // aliases KV stage 1
    #pragma unroll 1
    for (int r = 0; r < 4; ++r) {
        __syncthreads();
        if (wn == r) {
            #pragma unroll
            for (int nt = 0; nt < 8; ++nt) {
                int a0 = r0 * PO + nt * 8 + 2 * t4;
                int a1 = (r0 + 8) * PO + nt * 8 + 2 * t4;
                if (r == 0) {
                    accA[a0] = OfA[nt][0]; accA[a0 + 1] = OfA[nt][1];
                    accA[a1] = OfA[nt][2]; accA[a1 + 1] = OfA[nt][3];
                    accB[a0] = OfB[nt][0]; accB[a0 + 1] = OfB[nt][1];
                    accB[a1] = OfB[nt][2]; accB[a1 + 1] = OfB[nt][3];
                } else {
                    accA[a0] += OfA[nt][0]; accA[a0 + 1] += OfA[nt][1];
                    accA[a1] += OfA[nt][2]; accA[a1 + 1] += OfA[nt][3];
                    accB[a0] += OfB[nt][0]; accB[a0 + 1] += OfB[nt][1];
                    accB[a1] += OfB[nt][2]; accB[a1 + 1] += OfB[nt][3];
                }
            }
        }
    }
    __syncthreads();

    const size_t boff = (size_t)(b * Tt) * Hh;
    float* opA = out + boff + (size_t)qbaseA * Hh;
    float* opB = out + boff + (size_t)qbaseB * Hh;
    #pragma unroll
    for (int it = 0; it < 8; ++it) {
        int i = tid + it * 256;
        int r = i >> 6, dd = i & 63;
        opA[i] = accA[r * PO + dd] * __fdividef(1.0f, smf[O_LG + r]);
        opB[i] = accB[r * PO + dd] * __fdividef(1.0f, smf[O_LG + 32 + r]);
    }
}

extern "C" void kernel_launch(void* const* d_in, const int* in_sizes, int n_in,
                              void* d_out, int out_size)
{
    const float* x  = (const float*)d_in[0];
    const float* Wq = (const float*)d_in[1];
    const float* bq = (const float*)d_in[2];
    const float* Wk = (const float*)d_in[3];
    const float* bk = (const float*)d_in[4];
    const float* Wv = (const float*)d_in[5];
    const float* bv = (const float*)d_in[6];
    float* out = (float*)d_out;

    cudaFuncSetAttribute(qkv_mma, cudaFuncAttributeMaxDynamicSharedMemorySize,
                         QKV_SMEM_BYTES);
    cudaFuncSetAttribute(attn_mma, cudaFuncAttributeMaxDynamicSharedMemorySize,
                         ATTN_SMEM_BYTES);

    wsplit<<<192, 512>>>(Wq, Wk, Wv);
    qkv_mma<<<128, 256, QKV_SMEM_BYTES>>>(x, bq, bk, bv);
    attn_mma<<<dim3(32, 4), 256, ATTN_SMEM_BYTES>>>(out);
}